// round 4
// baseline (speedup 1.0000x reference)
#include <cuda_runtime.h>
#include <cuda_bf16.h>
#include <cstdint>

typedef unsigned long long ull;

#define BB 128
#define SS 512
#define HH 128
#define EPSM 8.673617379884035e-19f   // 2^-60, exact in bf16

// -------- static device scratch --------
static __device__ unsigned char g_code[(size_t)BB * SS * SS];
static __device__ float g_hbuf0[(size_t)BB * SS * HH];
static __device__ float g_hbuf1[(size_t)BB * SS * HH];
static __device__ float g_sa[BB * SS];
static __device__ float g_sb[BB * SS];

// ---------------- packed f32x2 helpers ----------------
__device__ __forceinline__ ull pk2(float lo, float hi) {
    ull r; asm("mov.b64 %0,{%1,%2};" : "=l"(r) : "f"(lo), "f"(hi)); return r;
}
__device__ __forceinline__ void upk2(float& lo, float& hi, ull v) {
    asm("mov.b64 {%0,%1},%2;" : "=f"(lo), "=f"(hi) : "l"(v));
}
__device__ __forceinline__ ull dup2(float c) {
    ull r; asm("mov.b64 %0,{%1,%1};" : "=l"(r) : "f"(c)); return r;
}
__device__ __forceinline__ ull fma2(ull a, ull b, ull c) {
    ull d; asm("fma.rn.f32x2 %0,%1,%2,%3;" : "=l"(d) : "l"(a), "l"(b), "l"(c)); return d;
}
__device__ __forceinline__ ull mul2(ull a, ull b) {
    ull d; asm("mul.rn.f32x2 %0,%1,%2;" : "=l"(d) : "l"(a), "l"(b)); return d;
}
__device__ __forceinline__ float rcpa(float x) {
    float r; asm("rcp.approx.f32 %0,%1;" : "=f"(r) : "f"(x)); return r;
}
__device__ __forceinline__ uint32_t bf2(float hi, float lo) {
    uint32_t r; asm("cvt.rn.bf16x2.f32 %0,%1,%2;" : "=r"(r) : "f"(hi), "f"(lo)); return r;
}

// packed tanh (Eigen rational), 2 lanes at once; rcp via MUFU
__device__ __forceinline__ ull tanh2(ull x) {
    const ull x2 = mul2(x, x);
    ull p = dup2(-2.76076847742355e-16f);
    p = fma2(p, x2, dup2(2.00018790482477e-13f));
    p = fma2(p, x2, dup2(-8.60467152213735e-11f));
    p = fma2(p, x2, dup2(5.12229709037114e-08f));
    p = fma2(p, x2, dup2(1.48572235717979e-05f));
    p = fma2(p, x2, dup2(6.37261928875436e-04f));
    p = fma2(p, x2, dup2(4.89352455891786e-03f));
    p = mul2(p, x);
    ull q = dup2(1.19825839466702e-06f);
    q = fma2(q, x2, dup2(1.18534705686654e-04f));
    q = fma2(q, x2, dup2(2.26843463243900e-03f));
    q = fma2(q, x2, dup2(4.89352518554385e-03f));
    float ql, qh; upk2(ql, qh, q);
    return mul2(p, pk2(rcpa(ql), rcpa(qh)));
}
__device__ __forceinline__ float clamp9(float x) {
    return fminf(8.5f, fmaxf(-8.5f, x));
}

// ---------------- tensor-core primitives ----------------
__device__ __forceinline__ void ldsm_x4(uint32_t r[4], uint32_t addr) {
    asm volatile("ldmatrix.sync.aligned.m8n8.x4.shared.b16 {%0,%1,%2,%3}, [%4];"
        : "=r"(r[0]), "=r"(r[1]), "=r"(r[2]), "=r"(r[3]) : "r"(addr));
}
__device__ __forceinline__ void ldsm_x4_t(uint32_t r[4], uint32_t addr) {
    asm volatile("ldmatrix.sync.aligned.m8n8.x4.trans.shared.b16 {%0,%1,%2,%3}, [%4];"
        : "=r"(r[0]), "=r"(r[1]), "=r"(r[2]), "=r"(r[3]) : "r"(addr));
}
__device__ __forceinline__ void mma16816(float acc[4], const uint32_t a[4],
                                         uint32_t b0, uint32_t b1) {
    asm volatile(
        "mma.sync.aligned.m16n8k16.row.col.f32.bf16.bf16.f32 "
        "{%0,%1,%2,%3}, {%4,%5,%6,%7}, {%8,%9}, {%0,%1,%2,%3};\n"
        : "+f"(acc[0]), "+f"(acc[1]), "+f"(acc[2]), "+f"(acc[3])
        : "r"(a[0]), "r"(a[1]), "r"(a[2]), "r"(a[3]), "r"(b0), "r"(b1));
}
__device__ __forceinline__ uint32_t bfbits(__nv_bfloat16 v) {
    return (uint32_t)__bfloat16_as_ushort(v);
}

// ---------------------------------------------------------------
// Kernel 1: pack adjacency into 2-bit codes
// ---------------------------------------------------------------
__global__ void pack_code_kernel(const float* __restrict__ adj) {
    __shared__ float tT[32][33];
    const int b = blockIdx.z;
    const int J = blockIdx.x * 32;
    const int I = blockIdx.y * 32;
    const int tx = threadIdx.x, ty = threadIdx.y;
    const float* A = adj + (size_t)b * SS * SS;

    tT[ty][tx] = A[(size_t)(J + ty) * SS + (I + tx)];
    float a = A[(size_t)(I + ty) * SS + (J + tx)];
    __syncthreads();

    unsigned char c = (a == 1.0f ? 1u : 0u) | (tT[tx][ty] == 1.0f ? 2u : 0u);
    g_code[((size_t)b * SS + (I + ty)) * SS + (J + tx)] = c;
}

// ---------------------------------------------------------------
// Kernel 2: sa = w1.h + bias, sb = w2.h
// ---------------------------------------------------------------
__global__ void sasb_kernel(const float* __restrict__ hin,
                            const float* __restrict__ w1,
                            const float* __restrict__ w2,
                            const float* __restrict__ bias_ptr) {
    const int tid  = threadIdx.x;
    const int lane = tid & 31;
    const int row  = blockIdx.x * 8 + (tid >> 5);
    if (row >= BB * SS) return;

    const float4 hv  = reinterpret_cast<const float4*>(hin)[(size_t)row * 32 + lane];
    const float4 w1v = reinterpret_cast<const float4*>(w1)[lane];
    const float4 w2v = reinterpret_cast<const float4*>(w2)[lane];

    float d1 = hv.x * w1v.x + hv.y * w1v.y + hv.z * w1v.z + hv.w * w1v.w;
    float d2 = hv.x * w2v.x + hv.y * w2v.y + hv.z * w2v.z + hv.w * w2v.w;
    #pragma unroll
    for (int off = 16; off > 0; off >>= 1) {
        d1 += __shfl_xor_sync(0xFFFFFFFFu, d1, off);
        d2 += __shfl_xor_sync(0xFFFFFFFFu, d2, off);
    }
    if (lane == 0) {
        g_sa[row] = d1 + bias_ptr[0];
        g_sb[row] = d2;
    }
}

// ---------------------------------------------------------------
// Kernel 3: fused scores + softmax + bf16-split MMA.
// 32 rows/block, 256 thr, smem 88KB -> occupancy 2 (phase overlap).
// P smem layout: row stride 1040B, 16B XOR swizzle within row.
// ---------------------------------------------------------------
#define LDPB 1040   // P row stride in BYTES (520 bf16)
#define LDHB 272    // H chunk row stride in BYTES (136 bf16)

#define OFF_SA   0
#define OFF_SB   2048
#define OFF_RSUM 4096
#define OFF_PHI  4224
#define OFF_PLO  (OFF_PHI + 32 * LDPB)     // 37504
#define OFF_HHI  (OFF_PLO + 32 * LDPB)     // 70784
#define OFF_HLO  (OFF_HHI + 32 * LDHB)     // 79488
#define SMEM_TOTAL (OFF_HLO + 32 * LDHB)   // 88192 bytes

__device__ __forceinline__ uint32_t pswz(uint32_t byteCol) {
    return byteCol ^ (((byteCol >> 7) & 7u) << 4);
}

__global__ __launch_bounds__(256, 2)
void fused_layer_kernel(const float* __restrict__ hin,
                        float* __restrict__ hout) {
    extern __shared__ char smem[];
    float* s_sa   = (float*)(smem + OFF_SA);
    float* s_sb   = (float*)(smem + OFF_SB);
    float* s_rsum = (float*)(smem + OFF_RSUM);
    const uint32_t smem_u32 = (uint32_t)__cvta_generic_to_shared(smem);

    const int b    = blockIdx.y;
    const int i0   = blockIdx.x * 32;
    const int tid  = threadIdx.x;
    const int lane = tid & 31;
    const int w    = tid >> 5;

    #pragma unroll
    for (int q = 0; q < 2; q++) {
        int j = q * 256 + tid;
        s_sa[j] = g_sa[b * SS + j];
        s_sb[j] = g_sb[b * SS + j];
    }
    __syncthreads();

    // ---- Phase E: exp-scores -> bf16 hi/lo P (swizzled) + row sums ----
    {
        const int r   = tid >> 3;          // local row 0..31
        const int sub = tid & 7;           // 8 threads/row, 64 j each
        const int gi  = i0 + r;
        const float sai = s_sa[gi];
        const float sbi = s_sb[gi];
        const unsigned char* crow = g_code + ((size_t)b * SS + gi) * SS + sub * 64;
        char* prow = smem + OFF_PHI + r * LDPB;
        char* lrow = smem + OFF_PLO + r * LDPB;
        const float2* sa2 = (const float2*)s_sa;
        const float2* sb2 = (const float2*)s_sb;

        float esum = 0.0f;
        #pragma unroll 4
        for (int it = 0; it < 16; it++) {
            const uchar4 cc = reinterpret_cast<const uchar4*>(crow)[it];
            const int jb = sub * 64 + it * 4;          // first of 4 j's
            const float2 sb01 = sb2[jb >> 1];
            const float2 sb23 = sb2[(jb >> 1) + 1];
            const float2 sa01 = sa2[jb >> 1];
            const float2 sa23 = sa2[(jb >> 1) + 1];

            // orientation 1: tanh(sai + sb_j); orientation 2: tanh(sa_j + sbi)
            ull X1a = pk2(clamp9(sai + sb01.x), clamp9(sai + sb01.y));
            ull X1b = pk2(clamp9(sai + sb23.x), clamp9(sai + sb23.y));
            ull X2a = pk2(clamp9(sa01.x + sbi), clamp9(sa01.y + sbi));
            ull X2b = pk2(clamp9(sa23.x + sbi), clamp9(sa23.y + sbi));
            float t1[4], t2[4];
            upk2(t1[0], t1[1], tanh2(X1a));
            upk2(t1[2], t1[3], tanh2(X1b));
            upk2(t2[0], t2[1], tanh2(X2a));
            upk2(t2[2], t2[3], tanh2(X2b));

            float e[4];
            #pragma unroll
            for (int k = 0; k < 4; k++) {
                const unsigned int c = (k == 0) ? cc.x : (k == 1) ? cc.y
                                      : (k == 2) ? cc.z : cc.w;
                const float f1 = (c & 1u) ? t1[k] : 0.0f;
                const float f2 = (c & 2u) ? t2[k] : 0.0f;
                float ev = __expf(0.5f * (f1 + f2));
                e[k] = c ? ev : EPSM;
                esum += e[k];
            }
            const uint32_t h01 = bf2(e[1], e[0]);
            const uint32_t h23 = bf2(e[3], e[2]);
            const float l0 = e[0] - __uint_as_float(h01 << 16);
            const float l1 = e[1] - __uint_as_float(h01 & 0xFFFF0000u);
            const float l2 = e[2] - __uint_as_float(h23 << 16);
            const float l3 = e[3] - __uint_as_float(h23 & 0xFFFF0000u);
            const uint32_t q01 = bf2(l1, l0);
            const uint32_t q23 = bf2(l3, l2);

            const uint32_t sw = pswz((uint32_t)(sub * 128 + it * 8));
            *(uint2*)(prow + sw) = make_uint2(h01, h23);
            *(uint2*)(lrow + sw) = make_uint2(q01, q23);
        }
        esum += __shfl_xor_sync(0xFFFFFFFFu, esum, 1);
        esum += __shfl_xor_sync(0xFFFFFFFFu, esum, 2);
        esum += __shfl_xor_sync(0xFFFFFFFFu, esum, 4);
        if (sub == 0) s_rsum[r] = esum;
    }
    __syncthreads();

    // ---- Phase B: acc[32x128] = P_split @ H_split ----
    const int mi = w & 1;          // 2 M tiles of 16 rows
    const int ni = w >> 1;         // 4 N quarters of 32 cols
    const int m0 = mi * 16;
    const uint32_t a_base = smem_u32 + (uint32_t)(m0 + (lane & 15)) * LDPB;
    const uint32_t a_cb0  = (uint32_t)((lane >> 4) * 16);
    const int brow = (lane & 7) + ((lane >> 3) & 1) * 8;   // 0..15
    const uint32_t b_cb = (uint32_t)((ni * 32 + (lane >> 4) * 8) * 2);
    const float4* h4 = reinterpret_cast<const float4*>(hin + (size_t)b * SS * HH);

    float acc[4][4];
    #pragma unroll
    for (int nf = 0; nf < 4; nf++)
        #pragma unroll
        for (int q = 0; q < 4; q++) acc[nf][q] = 0.0f;

    for (int kc = 0; kc < 16; kc++) {
        // stage H chunk [32 x 128] fp32 -> hi/lo bf16
        #pragma unroll
        for (int q = 0; q < 4; q++) {
            const int lin = q * 256 + tid;
            const int jj  = lin >> 5;
            const int c4  = lin & 31;
            const float4 hv = h4[(size_t)(kc * 32 + jj) * 32 + c4];
            __nv_bfloat16 h0 = __float2bfloat16_rn(hv.x);
            __nv_bfloat16 h1 = __float2bfloat16_rn(hv.y);
            __nv_bfloat16 h2 = __float2bfloat16_rn(hv.z);
            __nv_bfloat16 h3 = __float2bfloat16_rn(hv.w);
            __nv_bfloat16 l0 = __float2bfloat16_rn(hv.x - __bfloat162float(h0));
            __nv_bfloat16 l1 = __float2bfloat16_rn(hv.y - __bfloat162float(h1));
            __nv_bfloat16 l2 = __float2bfloat16_rn(hv.z - __bfloat162float(h2));
            __nv_bfloat16 l3 = __float2bfloat16_rn(hv.w - __bfloat162float(h3));
            uint2* dsth = (uint2*)(smem + OFF_HHI + jj * LDHB + c4 * 8);
            uint2* dstl = (uint2*)(smem + OFF_HLO + jj * LDHB + c4 * 8);
            *dsth = make_uint2(bfbits(h0) | (bfbits(h1) << 16),
                               bfbits(h2) | (bfbits(h3) << 16));
            *dstl = make_uint2(bfbits(l0) | (bfbits(l1) << 16),
                               bfbits(l2) | (bfbits(l3) << 16));
        }
        __syncthreads();

        #pragma unroll
        for (int ks = 0; ks < 2; ks++) {
            const uint32_t cb = a_cb0 + (uint32_t)((kc * 32 + ks * 16) * 2);
            const uint32_t sw = pswz(cb);
            uint32_t ahi[4], alo[4];
            ldsm_x4(ahi, a_base + OFF_PHI + sw);
            ldsm_x4(alo, a_base + OFF_PLO + sw);
            #pragma unroll
            for (int nn = 0; nn < 2; nn++) {
                const uint32_t baddr = smem_u32 + (uint32_t)((ks * 16 + brow) * LDHB)
                                     + b_cb + (uint32_t)(nn * 32);
                uint32_t bh[4], bl[4];
                ldsm_x4_t(bh, baddr + OFF_HHI);
                ldsm_x4_t(bl, baddr + OFF_HLO);
                mma16816(acc[2 * nn],     ahi, bh[0], bh[1]);
                mma16816(acc[2 * nn],     ahi, bl[0], bl[1]);
                mma16816(acc[2 * nn],     alo, bh[0], bh[1]);
                mma16816(acc[2 * nn + 1], ahi, bh[2], bh[3]);
                mma16816(acc[2 * nn + 1], ahi, bl[2], bl[3]);
                mma16816(acc[2 * nn + 1], alo, bh[2], bh[3]);
            }
        }
        __syncthreads();
    }

    // ---- epilogue: normalize by row sum, store fp32 ----
    const int r0 = m0 + (lane >> 2);
    const float inv0 = 1.0f / s_rsum[r0];
    const float inv1 = 1.0f / s_rsum[r0 + 8];
    float* outr0 = hout + ((size_t)b * SS + i0 + r0) * HH;
    #pragma unroll
    for (int nf = 0; nf < 4; nf++) {
        const int col = ni * 32 + nf * 8 + 2 * (lane & 3);
        *(float2*)(outr0 + col) = make_float2(acc[nf][0] * inv0, acc[nf][1] * inv0);
        *(float2*)(outr0 + 8 * HH + col) = make_float2(acc[nf][2] * inv1, acc[nf][3] * inv1);
    }
}

// ---------------------------------------------------------------
// Kernel 4: gather rows by alias_inputs
// ---------------------------------------------------------------
__global__ void gather_kernel(const float* __restrict__ hfin,
                              const int* __restrict__ alias,
                              float* __restrict__ out) {
    const int tid = blockIdx.x * blockDim.x + threadIdx.x;
    const int N4 = BB * SS * (HH / 4);
    if (tid >= N4) return;
    const int c4 = tid & 31;
    const int s  = (tid >> 5) & (SS - 1);
    const int b  = tid >> (5 + 9);
    const int a  = alias[b * SS + s];
    reinterpret_cast<float4*>(out)[tid] =
        reinterpret_cast<const float4*>(hfin)[((size_t)b * SS + a) * 32 + c4];
}

// ---------------------------------------------------------------
extern "C" void kernel_launch(void* const* d_in, const int* in_sizes, int n_in,
                              void* d_out, int out_size) {
    const float* hidden = (const float*)d_in[0];
    const float* adj    = (const float*)d_in[1];
    const int*   alias  = (const int*)d_in[2];
    const float* w1     = (const float*)d_in[3];
    const float* w2     = (const float*)d_in[4];
    const float* bias   = (const float*)d_in[5];
    float* out = (float*)d_out;

    cudaFuncSetAttribute(fused_layer_kernel,
                         cudaFuncAttributeMaxDynamicSharedMemorySize, SMEM_TOTAL);

    float* hb0;  cudaGetSymbolAddress((void**)&hb0, g_hbuf0);
    float* hb1;  cudaGetSymbolAddress((void**)&hb1, g_hbuf1);

    pack_code_kernel<<<dim3(SS / 32, SS / 32, BB), dim3(32, 32)>>>(adj);

    const float* cur = hidden;
    float* nxt = hb0;
    for (int l = 0; l < 2; l++) {
        sasb_kernel<<<(BB * SS) / 8, 256>>>(cur, w1, w2, bias);
        fused_layer_kernel<<<dim3(SS / 32, BB), 256, SMEM_TOTAL>>>(cur, nxt);
        cur = nxt;
        nxt = hb1;
    }

    const int N4 = BB * SS * (HH / 4);
    gather_kernel<<<(N4 + 255) / 256, 256>>>(cur, alias, out);
}

// round 5
// speedup vs baseline: 1.3552x; 1.3552x over previous
#include <cuda_runtime.h>
#include <cuda_bf16.h>
#include <cstdint>

typedef unsigned long long ull;

#define BB 128
#define SS 512
#define HH 128
#define EPSM 8.673617379884035e-19f   // 2^-60, exact in bf16

// -------- static device scratch --------
static __device__ unsigned char g_code[(size_t)BB * SS * SS];
static __device__ float g_hbuf0[(size_t)BB * SS * HH];
static __device__ float g_hbuf1[(size_t)BB * SS * HH];
static __device__ uint32_t g_hhi[2][(size_t)BB * SS * HH / 2];  // bf16x2 pairs
static __device__ uint32_t g_hlo[2][(size_t)BB * SS * HH / 2];
static __device__ float g_sa[BB * SS];
static __device__ float g_sb[BB * SS];

// ---------------- packed f32x2 helpers ----------------
__device__ __forceinline__ ull pk2(float lo, float hi) {
    ull r; asm("mov.b64 %0,{%1,%2};" : "=l"(r) : "f"(lo), "f"(hi)); return r;
}
__device__ __forceinline__ void upk2(float& lo, float& hi, ull v) {
    asm("mov.b64 {%0,%1},%2;" : "=f"(lo), "=f"(hi) : "l"(v));
}
__device__ __forceinline__ ull dup2(float c) {
    ull r; asm("mov.b64 %0,{%1,%1};" : "=l"(r) : "f"(c)); return r;
}
__device__ __forceinline__ ull fma2(ull a, ull b, ull c) {
    ull d; asm("fma.rn.f32x2 %0,%1,%2,%3;" : "=l"(d) : "l"(a), "l"(b), "l"(c)); return d;
}
__device__ __forceinline__ ull mul2(ull a, ull b) {
    ull d; asm("mul.rn.f32x2 %0,%1,%2;" : "=l"(d) : "l"(a), "l"(b)); return d;
}
__device__ __forceinline__ float rcpa(float x) {
    float r; asm("rcp.approx.f32 %0,%1;" : "=f"(r) : "f"(x)); return r;
}
__device__ __forceinline__ uint32_t bf2(float hi, float lo) {
    uint32_t r; asm("cvt.rn.bf16x2.f32 %0,%1,%2;" : "=r"(r) : "f"(hi), "f"(lo)); return r;
}
__device__ __forceinline__ ull tanh2(ull x) {
    const ull x2 = mul2(x, x);
    ull p = dup2(-2.76076847742355e-16f);
    p = fma2(p, x2, dup2(2.00018790482477e-13f));
    p = fma2(p, x2, dup2(-8.60467152213735e-11f));
    p = fma2(p, x2, dup2(5.12229709037114e-08f));
    p = fma2(p, x2, dup2(1.48572235717979e-05f));
    p = fma2(p, x2, dup2(6.37261928875436e-04f));
    p = fma2(p, x2, dup2(4.89352455891786e-03f));
    p = mul2(p, x);
    ull q = dup2(1.19825839466702e-06f);
    q = fma2(q, x2, dup2(1.18534705686654e-04f));
    q = fma2(q, x2, dup2(2.26843463243900e-03f));
    q = fma2(q, x2, dup2(4.89352518554385e-03f));
    float ql, qh; upk2(ql, qh, q);
    return mul2(p, pk2(rcpa(ql), rcpa(qh)));
}
__device__ __forceinline__ float clamp9(float x) {
    return fminf(8.5f, fmaxf(-8.5f, x));
}

// ---------------- mma / ldsm / cp.async ----------------
__device__ __forceinline__ void ldsm_x4(uint32_t r[4], uint32_t addr) {
    asm volatile("ldmatrix.sync.aligned.m8n8.x4.shared.b16 {%0,%1,%2,%3}, [%4];"
        : "=r"(r[0]), "=r"(r[1]), "=r"(r[2]), "=r"(r[3]) : "r"(addr));
}
__device__ __forceinline__ void ldsm_x4_t(uint32_t r[4], uint32_t addr) {
    asm volatile("ldmatrix.sync.aligned.m8n8.x4.trans.shared.b16 {%0,%1,%2,%3}, [%4];"
        : "=r"(r[0]), "=r"(r[1]), "=r"(r[2]), "=r"(r[3]) : "r"(addr));
}
__device__ __forceinline__ void mma16816(float acc[4], const uint32_t a[4],
                                         uint32_t b0, uint32_t b1) {
    asm volatile(
        "mma.sync.aligned.m16n8k16.row.col.f32.bf16.bf16.f32 "
        "{%0,%1,%2,%3}, {%4,%5,%6,%7}, {%8,%9}, {%0,%1,%2,%3};\n"
        : "+f"(acc[0]), "+f"(acc[1]), "+f"(acc[2]), "+f"(acc[3])
        : "r"(a[0]), "r"(a[1]), "r"(a[2]), "r"(a[3]), "r"(b0), "r"(b1));
}
__device__ __forceinline__ void cp16(uint32_t dst, const void* src) {
    asm volatile("cp.async.ca.shared.global [%0], [%1], 16;" :: "r"(dst), "l"(src));
}
#define CP_COMMIT() asm volatile("cp.async.commit_group;" ::: "memory")
#define CP_WAIT0()  asm volatile("cp.async.wait_group 0;" ::: "memory")

// ---------------------------------------------------------------
// Kernel 1: symmetric pack — each block handles tiles (I,J) and (J,I)
// ---------------------------------------------------------------
__global__ void pack_code_kernel(const float* __restrict__ adj) {
    __shared__ float tA[32][33], tB[32][33];
    const int b = blockIdx.z;
    const int J = blockIdx.x * 32;
    const int I = blockIdx.y * 32;
    if (J < I) return;
    const int tx = threadIdx.x, ty = threadIdx.y;
    const float* A = adj + (size_t)b * SS * SS;

    tA[ty][tx] = A[(size_t)(I + ty) * SS + (J + tx)];
    tB[ty][tx] = A[(size_t)(J + ty) * SS + (I + tx)];
    __syncthreads();

    unsigned char cIJ = (tA[ty][tx] == 1.0f ? 1u : 0u) | (tB[tx][ty] == 1.0f ? 2u : 0u);
    unsigned char cJI = (tB[ty][tx] == 1.0f ? 1u : 0u) | (tA[tx][ty] == 1.0f ? 2u : 0u);
    g_code[((size_t)b * SS + (I + ty)) * SS + (J + tx)] = cIJ;
    g_code[((size_t)b * SS + (J + ty)) * SS + (I + tx)] = cJI;
}

// ---------------------------------------------------------------
// Kernel 1b: split fp32 hidden into bf16 hi/lo pairs
// ---------------------------------------------------------------
__global__ void hsplit_kernel(const float* __restrict__ h,
                              uint32_t* __restrict__ hi, uint32_t* __restrict__ lo) {
    const int i = blockIdx.x * blockDim.x + threadIdx.x;   // over float4's
    const float4 v = reinterpret_cast<const float4*>(h)[i];
    const uint32_t h01 = bf2(v.y, v.x);
    const uint32_t h23 = bf2(v.w, v.z);
    const float l0 = v.x - __uint_as_float(h01 << 16);
    const float l1 = v.y - __uint_as_float(h01 & 0xFFFF0000u);
    const float l2 = v.z - __uint_as_float(h23 << 16);
    const float l3 = v.w - __uint_as_float(h23 & 0xFFFF0000u);
    reinterpret_cast<uint2*>(hi)[i] = make_uint2(h01, h23);
    reinterpret_cast<uint2*>(lo)[i] = make_uint2(bf2(l1, l0), bf2(l3, l2));
}

// ---------------------------------------------------------------
// Kernel 2: sa = w1.h + bias, sb = w2.h
// ---------------------------------------------------------------
__global__ void sasb_kernel(const float* __restrict__ hin,
                            const float* __restrict__ w1,
                            const float* __restrict__ w2,
                            const float* __restrict__ bias_ptr) {
    const int tid  = threadIdx.x;
    const int lane = tid & 31;
    const int row  = blockIdx.x * 8 + (tid >> 5);
    if (row >= BB * SS) return;

    const float4 hv  = reinterpret_cast<const float4*>(hin)[(size_t)row * 32 + lane];
    const float4 w1v = reinterpret_cast<const float4*>(w1)[lane];
    const float4 w2v = reinterpret_cast<const float4*>(w2)[lane];

    float d1 = hv.x * w1v.x + hv.y * w1v.y + hv.z * w1v.z + hv.w * w1v.w;
    float d2 = hv.x * w2v.x + hv.y * w2v.y + hv.z * w2v.z + hv.w * w2v.w;
    #pragma unroll
    for (int off = 16; off > 0; off >>= 1) {
        d1 += __shfl_xor_sync(0xFFFFFFFFu, d1, off);
        d2 += __shfl_xor_sync(0xFFFFFFFFu, d2, off);
    }
    if (lane == 0) {
        g_sa[row] = d1 + bias_ptr[0];
        g_sb[row] = d2;
    }
}

// ---------------------------------------------------------------
// score quad: 4 elems -> bf16 hi/lo pairs + partial sum
// ---------------------------------------------------------------
__device__ __forceinline__ float quad4(uint32_t c4, const float4 sa4, const float4 sb4,
                                       const float sai, const float sbi,
                                       uint32_t& h01, uint32_t& h23,
                                       uint32_t& l01, uint32_t& l23) {
    ull X1a = pk2(clamp9(sai + sb4.x), clamp9(sai + sb4.y));
    ull X1b = pk2(clamp9(sai + sb4.z), clamp9(sai + sb4.w));
    ull X2a = pk2(clamp9(sa4.x + sbi), clamp9(sa4.y + sbi));
    ull X2b = pk2(clamp9(sa4.z + sbi), clamp9(sa4.w + sbi));
    float t1[4], t2[4];
    upk2(t1[0], t1[1], tanh2(X1a));
    upk2(t1[2], t1[3], tanh2(X1b));
    upk2(t2[0], t2[1], tanh2(X2a));
    upk2(t2[2], t2[3], tanh2(X2b));
    float e[4]; float es = 0.0f;
    #pragma unroll
    for (int k = 0; k < 4; k++) {
        const uint32_t c = (c4 >> (8 * k)) & 0xFFu;
        const float f1 = (c & 1u) ? t1[k] : 0.0f;
        const float f2 = (c & 2u) ? t2[k] : 0.0f;
        float ev = __expf(0.5f * (f1 + f2));
        e[k] = c ? ev : EPSM;
        es += e[k];
    }
    h01 = bf2(e[1], e[0]);
    h23 = bf2(e[3], e[2]);
    const float l0 = e[0] - __uint_as_float(h01 << 16);
    const float l1 = e[1] - __uint_as_float(h01 & 0xFFFF0000u);
    const float l2 = e[2] - __uint_as_float(h23 << 16);
    const float l3 = e[3] - __uint_as_float(h23 & 0xFFFF0000u);
    l01 = bf2(l1, l0);
    l23 = bf2(l3, l2);
    return es;
}

// ---------------------------------------------------------------
// Kernel 3: fused, chunk-pipelined. 64 rows/block, 256 thr, occ 2.
// smem: sa|sb|rsum | P[2buf][hi/lo][64r x 128B, row-XOR swz] | H[2buf][hi/lo][64 x 272B]
// ---------------------------------------------------------------
#define OFF_SA   0
#define OFF_SB   2048
#define OFF_RSUM 4096
#define OFF_P    4352
#define P_HALF   8192
#define P_BUF    16384
#define OFF_H    37120
#define H_HALF   17408
#define H_BUF    34816
#define SMEM_TOTAL 106752
#define LDHB 272

__global__ __launch_bounds__(256, 2)
void fused_layer_kernel(const uint32_t* __restrict__ hhi_in,
                        const uint32_t* __restrict__ hlo_in,
                        float* __restrict__ hout,
                        uint32_t* __restrict__ hhi_out,
                        uint32_t* __restrict__ hlo_out) {
    extern __shared__ char smem[];
    float* s_sa   = (float*)(smem + OFF_SA);
    float* s_sb   = (float*)(smem + OFF_SB);
    float* s_rsum = (float*)(smem + OFF_RSUM);
    const uint32_t su = (uint32_t)__cvta_generic_to_shared(smem);

    const int b    = blockIdx.y;
    const int i0   = blockIdx.x * 64;
    const int tid  = threadIdx.x;
    const int lane = tid & 31;
    const int w    = tid >> 5;

    #pragma unroll
    for (int q = 0; q < 2; q++) {
        int j = q * 256 + tid;
        s_sa[j] = g_sa[b * SS + j];
        s_sb[j] = g_sb[b * SS + j];
    }

    const uint32_t* hhiB = hhi_in + (size_t)b * SS * (HH / 2);
    const uint32_t* hloB = hlo_in + (size_t)b * SS * (HH / 2);

    // issue cp.async for H chunk 0 -> buf 0
    #pragma unroll
    for (int t = 0; t < 4; t++) {
        const int idx = t * 256 + tid;
        const int k = idx >> 4, g = idx & 15;
        const uint32_t d = su + OFF_H + k * LDHB + g * 16;
        cp16(d,          hhiB + (size_t)k * 64 + g * 4);
        cp16(d + H_HALF, hloB + (size_t)k * 64 + g * 4);
    }
    CP_COMMIT();
    __syncthreads();   // sa/sb visible

    // Phase-E per-thread constants
    const int er = tid >> 2;            // local row 0..63
    const int eq = tid & 3;
    const float sai = s_sa[i0 + er];
    const float sbi = s_sb[i0 + er];
    const unsigned char* crow = g_code + ((size_t)b * SS + i0 + er) * SS;
    float esum = 0.0f;

    // E for chunk kc -> P buf (kc&1)
    auto e_chunk = [&](int kc) {
        char* ph = smem + OFF_P + (kc & 1) * P_BUF + er * 128;
        char* pl = ph + P_HALF;
        #pragma unroll
        for (int sh = 0; sh < 2; sh++) {
            const int seg = eq + sh * 4;            // 16B unit 0..7
            const int jg0 = kc * 64 + seg * 8;
            const ull codes = *(const ull*)(crow + jg0);
            const float4 sb0 = *(const float4*)(s_sb + jg0);
            const float4 sb1 = *(const float4*)(s_sb + jg0 + 4);
            const float4 sa0 = *(const float4*)(s_sa + jg0);
            const float4 sa1 = *(const float4*)(s_sa + jg0 + 4);
            uint32_t h0, h1, h2, h3, l0, l1, l2, l3;
            esum += quad4((uint32_t)codes,         sa0, sb0, sai, sbi, h0, h1, l0, l1);
            esum += quad4((uint32_t)(codes >> 32), sa1, sb1, sai, sbi, h2, h3, l2, l3);
            const uint32_t phys = ((uint32_t)seg ^ (uint32_t)(er & 7)) * 16u;
            *(uint4*)(ph + phys) = make_uint4(h0, h1, h2, h3);
            *(uint4*)(pl + phys) = make_uint4(l0, l1, l2, l3);
        }
    };

    e_chunk(0);
    CP_WAIT0();
    __syncthreads();

    // MMA constants (R3-proven fragment mapping)
    const int mi = w & 3;                 // 4 M tiles of 16 rows
    const int ni = w >> 2;                // 2 N halves of 64 cols
    const int m0 = mi * 16;
    const int arow = m0 + (lane & 15);
    const int aunit0 = (lane >> 4);       // 0/1
    const int brow = (lane & 7) + ((lane >> 3) & 1) * 8;
    const uint32_t b_cb = (uint32_t)((ni * 64 + (lane >> 4) * 8) * 2);

    float acc[8][4];
    #pragma unroll
    for (int nf = 0; nf < 8; nf++)
        #pragma unroll
        for (int q = 0; q < 4; q++) acc[nf][q] = 0.0f;

    for (int kc = 0; kc < 8; kc++) {
        if (kc < 7) {
            const int nb = (kc + 1) & 1;
            #pragma unroll
            for (int t = 0; t < 4; t++) {
                const int idx = t * 256 + tid;
                const int k = idx >> 4, g = idx & 15;
                const uint32_t d = su + OFF_H + nb * H_BUF + k * LDHB + g * 16;
                const size_t src = (size_t)((kc + 1) * 64 + k) * 64 + g * 4;
                cp16(d,          hhiB + src);
                cp16(d + H_HALF, hloB + src);
            }
            CP_COMMIT();
        }

        // MMA on chunk kc
        {
            const uint32_t pb = su + OFF_P + (kc & 1) * P_BUF + arow * 128;
            const uint32_t hb = su + OFF_H + (kc & 1) * H_BUF;
            #pragma unroll
            for (int s = 0; s < 4; s++) {
                const uint32_t phys = (((uint32_t)(s * 2 + aunit0)) ^ (uint32_t)(arow & 7)) * 16u;
                uint32_t ahi[4], alo[4];
                ldsm_x4(ahi, pb + phys);
                ldsm_x4(alo, pb + P_HALF + phys);
                #pragma unroll
                for (int nn = 0; nn < 4; nn++) {
                    const uint32_t baddr = hb + (uint32_t)((s * 16 + brow) * LDHB)
                                         + b_cb + (uint32_t)(nn * 32);
                    uint32_t bh[4], bl[4];
                    ldsm_x4_t(bh, baddr);
                    ldsm_x4_t(bl, baddr + H_HALF);
                    mma16816(acc[2 * nn],     ahi, bh[0], bh[1]);
                    mma16816(acc[2 * nn],     ahi, bl[0], bl[1]);
                    mma16816(acc[2 * nn],     alo, bh[0], bh[1]);
                    mma16816(acc[2 * nn + 1], ahi, bh[2], bh[3]);
                    mma16816(acc[2 * nn + 1], ahi, bl[2], bl[3]);
                    mma16816(acc[2 * nn + 1], alo, bh[2], bh[3]);
                }
            }
        }

        if (kc < 7) {
            e_chunk(kc + 1);
            CP_WAIT0();
        }
        __syncthreads();
    }

    // row sums
    esum += __shfl_xor_sync(0xFFFFFFFFu, esum, 1);
    esum += __shfl_xor_sync(0xFFFFFFFFu, esum, 2);
    if (eq == 0) s_rsum[er] = esum;
    __syncthreads();

    // epilogue: normalize, store fp32 + bf16 hi/lo for next layer
    const int r0 = m0 + (lane >> 2);
    const float inv0 = 1.0f / s_rsum[r0];
    const float inv1 = 1.0f / s_rsum[r0 + 8];
    const size_t gr0 = ((size_t)b * SS + i0 + r0) * HH;
    const size_t gr1 = gr0 + 8 * HH;
    #pragma unroll
    for (int nf = 0; nf < 8; nf++) {
        const int col = ni * 64 + nf * 8 + 2 * (lane & 3);
        const float v0 = acc[nf][0] * inv0, v1 = acc[nf][1] * inv0;
        const float v2 = acc[nf][2] * inv1, v3 = acc[nf][3] * inv1;
        *(float2*)(hout + gr0 + col) = make_float2(v0, v1);
        *(float2*)(hout + gr1 + col) = make_float2(v2, v3);

        uint32_t hp0 = bf2(v1, v0);
        uint32_t hp1 = bf2(v3, v2);
        const float a0 = v0 - __uint_as_float(hp0 << 16);
        const float a1 = v1 - __uint_as_float(hp0 & 0xFFFF0000u);
        const float a2 = v2 - __uint_as_float(hp1 << 16);
        const float a3 = v3 - __uint_as_float(hp1 & 0xFFFF0000u);
        hhi_out[(gr0 + col) >> 1] = hp0;
        hlo_out[(gr0 + col) >> 1] = bf2(a1, a0);
        hhi_out[(gr1 + col) >> 1] = hp1;
        hlo_out[(gr1 + col) >> 1] = bf2(a3, a2);
    }
}

// ---------------------------------------------------------------
// Kernel 4: gather rows by alias_inputs
// ---------------------------------------------------------------
__global__ void gather_kernel(const float* __restrict__ hfin,
                              const int* __restrict__ alias,
                              float* __restrict__ out) {
    const int tid = blockIdx.x * blockDim.x + threadIdx.x;
    const int N4 = BB * SS * (HH / 4);
    if (tid >= N4) return;
    const int c4 = tid & 31;
    const int s  = (tid >> 5) & (SS - 1);
    const int b  = tid >> (5 + 9);
    const int a  = alias[b * SS + s];
    reinterpret_cast<float4*>(out)[tid] =
        reinterpret_cast<const float4*>(hfin)[((size_t)b * SS + a) * 32 + c4];
}

// ---------------------------------------------------------------
extern "C" void kernel_launch(void* const* d_in, const int* in_sizes, int n_in,
                              void* d_out, int out_size) {
    const float* hidden = (const float*)d_in[0];
    const float* adj    = (const float*)d_in[1];
    const int*   alias  = (const int*)d_in[2];
    const float* w1     = (const float*)d_in[3];
    const float* w2     = (const float*)d_in[4];
    const float* bias   = (const float*)d_in[5];
    float* out = (float*)d_out;

    cudaFuncSetAttribute(fused_layer_kernel,
                         cudaFuncAttributeMaxDynamicSharedMemorySize, SMEM_TOTAL);

    float* hb0;  cudaGetSymbolAddress((void**)&hb0, g_hbuf0);
    float* hb1;  cudaGetSymbolAddress((void**)&hb1, g_hbuf1);
    uint32_t* hhi; cudaGetSymbolAddress((void**)&hhi, g_hhi);
    uint32_t* hlo; cudaGetSymbolAddress((void**)&hlo, g_hlo);
    const size_t HC = (size_t)BB * SS * HH / 2;

    pack_code_kernel<<<dim3(SS / 32, SS / 32, BB), dim3(32, 32)>>>(adj);
    hsplit_kernel<<<(BB * SS * HH / 4) / 256, 256>>>(hidden, hhi, hlo);

    // layer 1: read split buf0 -> write hb0 fp32 + split buf1
    sasb_kernel<<<(BB * SS) / 8, 256>>>(hidden, w1, w2, bias);
    fused_layer_kernel<<<dim3(SS / 64, BB), 256, SMEM_TOTAL>>>(
        hhi, hlo, hb0, hhi + HC, hlo + HC);

    // layer 2: read split buf1 -> write hb1 fp32 + split buf0 (unused)
    sasb_kernel<<<(BB * SS) / 8, 256>>>(hb0, w1, w2, bias);
    fused_layer_kernel<<<dim3(SS / 64, BB), 256, SMEM_TOTAL>>>(
        hhi + HC, hlo + HC, hb1, hhi, hlo);

    const int N4 = BB * SS * (HH / 4);
    gather_kernel<<<(N4 + 255) / 256, 256>>>(hb1, alias, out);
}

// round 7
// speedup vs baseline: 1.7212x; 1.2701x over previous
#include <cuda_runtime.h>
#include <cuda_bf16.h>
#include <cstdint>

typedef unsigned long long ull;

#define BB 128
#define SS 512
#define HH 128
#define EPSM 8.673617379884035e-19f   // 2^-60, exact in bf16

// -------- static device scratch --------
static __device__ unsigned char g_code[(size_t)BB * SS * SS];
static __device__ float g_hbuf0[(size_t)BB * SS * HH];
static __device__ float g_hbuf1[(size_t)BB * SS * HH];
static __device__ uint32_t g_hhi[2][(size_t)BB * SS * HH / 2];  // bf16x2 pairs
static __device__ uint32_t g_hlo[2][(size_t)BB * SS * HH / 2];
static __device__ float g_sa[BB * SS];
static __device__ float g_sb[BB * SS];

// ---------------- fast math ----------------
__device__ __forceinline__ float tanha(float x) {
    float r; asm("tanh.approx.f32 %0,%1;" : "=f"(r) : "f"(x)); return r;
}
__device__ __forceinline__ float ex2a(float x) {
    float r; asm("ex2.approx.f32 %0,%1;" : "=f"(r) : "f"(x)); return r;
}
__device__ __forceinline__ uint32_t bf2(float hi, float lo) {
    uint32_t r; asm("cvt.rn.bf16x2.f32 %0,%1,%2;" : "=r"(r) : "f"(hi), "f"(lo)); return r;
}

// ---------------- mma / ldsm / cp.async ----------------
__device__ __forceinline__ void ldsm_x4(uint32_t r[4], uint32_t addr) {
    asm volatile("ldmatrix.sync.aligned.m8n8.x4.shared.b16 {%0,%1,%2,%3}, [%4];"
        : "=r"(r[0]), "=r"(r[1]), "=r"(r[2]), "=r"(r[3]) : "r"(addr));
}
__device__ __forceinline__ void ldsm_x4_t(uint32_t r[4], uint32_t addr) {
    asm volatile("ldmatrix.sync.aligned.m8n8.x4.trans.shared.b16 {%0,%1,%2,%3}, [%4];"
        : "=r"(r[0]), "=r"(r[1]), "=r"(r[2]), "=r"(r[3]) : "r"(addr));
}
__device__ __forceinline__ void mma16816(float acc[4], const uint32_t a[4],
                                         uint32_t b0, uint32_t b1) {
    asm volatile(
        "mma.sync.aligned.m16n8k16.row.col.f32.bf16.bf16.f32 "
        "{%0,%1,%2,%3}, {%4,%5,%6,%7}, {%8,%9}, {%0,%1,%2,%3};\n"
        : "+f"(acc[0]), "+f"(acc[1]), "+f"(acc[2]), "+f"(acc[3])
        : "r"(a[0]), "r"(a[1]), "r"(a[2]), "r"(a[3]), "r"(b0), "r"(b1));
}
__device__ __forceinline__ void cp16(uint32_t dst, const void* src) {
    asm volatile("cp.async.cg.shared.global [%0], [%1], 16;" :: "r"(dst), "l"(src));
}
#define CP_COMMIT() asm volatile("cp.async.commit_group;" ::: "memory")
#define CP_WAIT0()  asm volatile("cp.async.wait_group 0;" ::: "memory")

// ---------------------------------------------------------------
// Kernel 1: symmetric pack
// ---------------------------------------------------------------
__global__ void pack_code_kernel(const float* __restrict__ adj) {
    __shared__ float tA[32][33], tB[32][33];
    const int b = blockIdx.z;
    const int J = blockIdx.x * 32;
    const int I = blockIdx.y * 32;
    if (J < I) return;
    const int tx = threadIdx.x, ty = threadIdx.y;
    const float* A = adj + (size_t)b * SS * SS;

    tA[ty][tx] = A[(size_t)(I + ty) * SS + (J + tx)];
    tB[ty][tx] = A[(size_t)(J + ty) * SS + (I + tx)];
    __syncthreads();

    unsigned char cIJ = (tA[ty][tx] == 1.0f ? 1u : 0u) | (tB[tx][ty] == 1.0f ? 2u : 0u);
    unsigned char cJI = (tB[ty][tx] == 1.0f ? 1u : 0u) | (tA[tx][ty] == 1.0f ? 2u : 0u);
    g_code[((size_t)b * SS + (I + ty)) * SS + (J + tx)] = cIJ;
    g_code[((size_t)b * SS + (J + ty)) * SS + (I + tx)] = cJI;
}

// ---------------------------------------------------------------
// Kernel 1b: split fp32 hidden into bf16 hi/lo pairs
// ---------------------------------------------------------------
__global__ void hsplit_kernel(const float* __restrict__ h,
                              uint32_t* __restrict__ hi, uint32_t* __restrict__ lo) {
    const int i = blockIdx.x * blockDim.x + threadIdx.x;   // over float4's
    const float4 v = reinterpret_cast<const float4*>(h)[i];
    const uint32_t h01 = bf2(v.y, v.x);
    const uint32_t h23 = bf2(v.w, v.z);
    const float l0 = v.x - __uint_as_float(h01 << 16);
    const float l1 = v.y - __uint_as_float(h01 & 0xFFFF0000u);
    const float l2 = v.z - __uint_as_float(h23 << 16);
    const float l3 = v.w - __uint_as_float(h23 & 0xFFFF0000u);
    reinterpret_cast<uint2*>(hi)[i] = make_uint2(h01, h23);
    reinterpret_cast<uint2*>(lo)[i] = make_uint2(bf2(l1, l0), bf2(l3, l2));
}

// ---------------------------------------------------------------
// Kernel 2: sa = w1.h + bias, sb = w2.h
// ---------------------------------------------------------------
__global__ void sasb_kernel(const float* __restrict__ hin,
                            const float* __restrict__ w1,
                            const float* __restrict__ w2,
                            const float* __restrict__ bias_ptr) {
    const int tid  = threadIdx.x;
    const int lane = tid & 31;
    const int row  = blockIdx.x * 8 + (tid >> 5);
    if (row >= BB * SS) return;

    const float4 hv  = reinterpret_cast<const float4*>(hin)[(size_t)row * 32 + lane];
    const float4 w1v = reinterpret_cast<const float4*>(w1)[lane];
    const float4 w2v = reinterpret_cast<const float4*>(w2)[lane];

    float d1 = hv.x * w1v.x + hv.y * w1v.y + hv.z * w1v.z + hv.w * w1v.w;
    float d2 = hv.x * w2v.x + hv.y * w2v.y + hv.z * w2v.z + hv.w * w2v.w;
    #pragma unroll
    for (int off = 16; off > 0; off >>= 1) {
        d1 += __shfl_xor_sync(0xFFFFFFFFu, d1, off);
        d2 += __shfl_xor_sync(0xFFFFFFFFu, d2, off);
    }
    if (lane == 0) {
        g_sa[row] = d1 + bias_ptr[0];
        g_sb[row] = d2;
    }
}

// ---------------------------------------------------------------
// score quad (MUFU version): 4 elems -> bf16 hi/lo pairs + partial sum
// ---------------------------------------------------------------
#define HLOG2E 0.721347520444f   // 0.5 * log2(e)

__device__ __forceinline__ float quad4(uint32_t c4, const float4 sa4, const float4 sb4,
                                       const float sai, const float sbi,
                                       uint32_t& h01, uint32_t& h23,
                                       uint32_t& l01, uint32_t& l23) {
    float t1[4], t2[4];
    t1[0] = tanha(sai + sb4.x);  t1[1] = tanha(sai + sb4.y);
    t1[2] = tanha(sai + sb4.z);  t1[3] = tanha(sai + sb4.w);
    t2[0] = tanha(sa4.x + sbi);  t2[1] = tanha(sa4.y + sbi);
    t2[2] = tanha(sa4.z + sbi);  t2[3] = tanha(sa4.w + sbi);
    float e[4]; float es = 0.0f;
    #pragma unroll
    for (int k = 0; k < 4; k++) {
        const uint32_t c = (c4 >> (8 * k)) & 0xFFu;
        const float f1 = (c & 1u) ? t1[k] : 0.0f;
        const float f2 = (c & 2u) ? t2[k] : 0.0f;
        const float ev = ex2a((f1 + f2) * HLOG2E);
        e[k] = c ? ev : EPSM;
        es += e[k];
    }
    h01 = bf2(e[1], e[0]);
    h23 = bf2(e[3], e[2]);
    const float l0 = e[0] - __uint_as_float(h01 << 16);
    const float l1 = e[1] - __uint_as_float(h01 & 0xFFFF0000u);
    const float l2 = e[2] - __uint_as_float(h23 << 16);
    const float l3 = e[3] - __uint_as_float(h23 & 0xFFFF0000u);
    l01 = bf2(l1, l0);
    l23 = bf2(l3, l2);
    return es;
}

// ---------------------------------------------------------------
// Kernel 3: fused. 64 rows/block, 256 thr, single-buffered P and H,
// smem 55.8KB -> 3 blocks/SM (launch_bounds(256,3)).
// Per chunk: E(kc) -> wait/sync -> MMA(kc) -> sync -> prefetch H(kc+1)
// ---------------------------------------------------------------
#define OFF_SA   0
#define OFF_SB   2048
#define OFF_RS   4096
#define OFF_P    4608
#define P_PART   8192
#define OFF_H    20992
#define H_PART   17408
#define SMEM_TOTAL 55808
#define LDHB 272

__global__ __launch_bounds__(256, 3)
void fused_layer_kernel(const uint32_t* __restrict__ hhi_in,
                        const uint32_t* __restrict__ hlo_in,
                        float* __restrict__ hout,
                        uint32_t* __restrict__ hhi_out,
                        uint32_t* __restrict__ hlo_out,
                        int write_split) {
    extern __shared__ char smem[];
    float* s_sa   = (float*)(smem + OFF_SA);
    float* s_sb   = (float*)(smem + OFF_SB);
    float* s_rsum = (float*)(smem + OFF_RS);
    const uint32_t su = (uint32_t)__cvta_generic_to_shared(smem);

    const int b    = blockIdx.y;
    const int i0   = blockIdx.x * 64;
    const int tid  = threadIdx.x;
    const int lane = tid & 31;
    const int w    = tid >> 5;

    #pragma unroll
    for (int q = 0; q < 2; q++) {
        int j = q * 256 + tid;
        s_sa[j] = g_sa[b * SS + j];
        s_sb[j] = g_sb[b * SS + j];
    }

    const uint32_t* hhiB = hhi_in + (size_t)b * SS * (HH / 2);
    const uint32_t* hloB = hlo_in + (size_t)b * SS * (HH / 2);

    // prefetch H chunk 0
    #pragma unroll
    for (int t = 0; t < 4; t++) {
        const int idx = t * 256 + tid;
        const int k = idx >> 4, g = idx & 15;
        const uint32_t d = su + OFF_H + k * LDHB + g * 16;
        cp16(d,          hhiB + (size_t)k * 64 + g * 4);
        cp16(d + H_PART, hloB + (size_t)k * 64 + g * 4);
    }
    CP_COMMIT();
    __syncthreads();   // sa/sb visible

    // Phase-E constants: 4 threads/row
    const int er = tid >> 2;
    const int eq = tid & 3;
    const float sai = s_sa[i0 + er];
    const float sbi = s_sb[i0 + er];
    const unsigned char* crow = g_code + ((size_t)b * SS + i0 + er) * SS;
    float esum = 0.0f;

    // MMA constants (R5-proven fragment mapping)
    const int mi = w & 3;                 // 4 M tiles of 16 rows
    const int ni = w >> 2;                // 2 N halves of 64 cols
    const int m0 = mi * 16;
    const int arow = m0 + (lane & 15);
    const int aunit0 = (lane >> 4);       // 0/1
    const int brow = (lane & 7) + ((lane >> 3) & 1) * 8;
    const uint32_t b_cb = (uint32_t)((ni * 64 + (lane >> 4) * 8) * 2);

    float acc[8][4];
    #pragma unroll
    for (int nf = 0; nf < 8; nf++)
        #pragma unroll
        for (int q = 0; q < 4; q++) acc[nf][q] = 0.0f;

    for (int kc = 0; kc < 8; kc++) {
        // ---- Phase E for chunk kc -> P (single buffer; MMA(kc-1) done) ----
        {
            char* ph = smem + OFF_P + er * 128;
            char* pl = ph + P_PART;
            #pragma unroll
            for (int sh = 0; sh < 2; sh++) {
                const int seg = eq + sh * 4;            // 16B unit 0..7
                const int j0 = kc * 64 + seg * 8;
                const ull codes = *(const ull*)(crow + j0);
                const float4 sb0 = *(const float4*)(s_sb + j0);
                const float4 sb1 = *(const float4*)(s_sb + j0 + 4);
                const float4 sa0 = *(const float4*)(s_sa + j0);
                const float4 sa1 = *(const float4*)(s_sa + j0 + 4);
                uint32_t h0, h1, h2, h3, l0, l1, l2, l3;
                esum += quad4((uint32_t)codes,         sa0, sb0, sai, sbi, h0, h1, l0, l1);
                esum += quad4((uint32_t)(codes >> 32), sa1, sb1, sai, sbi, h2, h3, l2, l3);
                const uint32_t phys = ((uint32_t)(seg ^ (er & 7))) * 16u;
                *(uint4*)(ph + phys) = make_uint4(h0, h1, h2, h3);
                *(uint4*)(pl + phys) = make_uint4(l0, l1, l2, l3);
            }
        }

        CP_WAIT0();          // H(kc) arrived
        __syncthreads();     // P(kc) + H(kc) visible to all

        // ---- MMA on chunk kc ----
        {
            const uint32_t pb = su + OFF_P + arow * 128;
            const uint32_t hb = su + OFF_H;
            #pragma unroll
            for (int s = 0; s < 4; s++) {
                const uint32_t phys = (((uint32_t)(s * 2 + aunit0)) ^ (uint32_t)(arow & 7)) * 16u;
                uint32_t ahi[4], alo[4];
                ldsm_x4(ahi, pb + phys);
                ldsm_x4(alo, pb + P_PART + phys);
                #pragma unroll
                for (int nn = 0; nn < 4; nn++) {
                    const uint32_t baddr = hb + (uint32_t)((s * 16 + brow) * LDHB)
                                         + b_cb + (uint32_t)(nn * 32);
                    uint32_t bh[4], bl[4];
                    ldsm_x4_t(bh, baddr);
                    ldsm_x4_t(bl, baddr + H_PART);
                    mma16816(acc[2 * nn],     ahi, bh[0], bh[1]);
                    mma16816(acc[2 * nn],     ahi, bl[0], bl[1]);
                    mma16816(acc[2 * nn],     alo, bh[0], bh[1]);
                    mma16816(acc[2 * nn + 1], ahi, bh[2], bh[3]);
                    mma16816(acc[2 * nn + 1], ahi, bl[2], bl[3]);
                    mma16816(acc[2 * nn + 1], alo, bh[2], bh[3]);
                }
            }
        }

        __syncthreads();     // MMA reads of P/H complete

        if (kc < 7) {
            #pragma unroll
            for (int t = 0; t < 4; t++) {
                const int idx = t * 256 + tid;
                const int k = idx >> 4, g = idx & 15;
                const uint32_t d = su + OFF_H + k * LDHB + g * 16;
                const size_t src = (size_t)((kc + 1) * 64 + k) * 64 + g * 4;
                cp16(d,          hhiB + src);
                cp16(d + H_PART, hloB + src);
            }
            CP_COMMIT();
        }
    }

    // row sums
    esum += __shfl_xor_sync(0xFFFFFFFFu, esum, 1);
    esum += __shfl_xor_sync(0xFFFFFFFFu, esum, 2);
    if (eq == 0) s_rsum[er] = esum;
    __syncthreads();

    // epilogue: normalize, store fp32 + bf16 hi/lo for next layer
    const int r0 = m0 + (lane >> 2);
    const float inv0 = 1.0f / s_rsum[r0];
    const float inv1 = 1.0f / s_rsum[r0 + 8];
    const size_t gr0 = ((size_t)b * SS + i0 + r0) * HH;
    const size_t gr1 = gr0 + 8 * HH;
    #pragma unroll
    for (int nf = 0; nf < 8; nf++) {
        const int col = ni * 64 + nf * 8 + 2 * (lane & 3);
        const float v0 = acc[nf][0] * inv0, v1 = acc[nf][1] * inv0;
        const float v2 = acc[nf][2] * inv1, v3 = acc[nf][3] * inv1;
        *(float2*)(hout + gr0 + col) = make_float2(v0, v1);
        *(float2*)(hout + gr1 + col) = make_float2(v2, v3);

        if (write_split) {
            uint32_t hp0 = bf2(v1, v0);
            uint32_t hp1 = bf2(v3, v2);
            const float a0 = v0 - __uint_as_float(hp0 << 16);
            const float a1 = v1 - __uint_as_float(hp0 & 0xFFFF0000u);
            const float a2 = v2 - __uint_as_float(hp1 << 16);
            const float a3 = v3 - __uint_as_float(hp1 & 0xFFFF0000u);
            hhi_out[(gr0 + col) >> 1] = hp0;
            hlo_out[(gr0 + col) >> 1] = bf2(a1, a0);
            hhi_out[(gr1 + col) >> 1] = hp1;
            hlo_out[(gr1 + col) >> 1] = bf2(a3, a2);
        }
    }
}

// ---------------------------------------------------------------
// Kernel 4: gather rows by alias_inputs
// ---------------------------------------------------------------
__global__ void gather_kernel(const float* __restrict__ hfin,
                              const int* __restrict__ alias,
                              float* __restrict__ out) {
    const int tid = blockIdx.x * blockDim.x + threadIdx.x;
    const int N4 = BB * SS * (HH / 4);
    if (tid >= N4) return;
    const int c4 = tid & 31;
    const int s  = (tid >> 5) & (SS - 1);
    const int b  = tid >> (5 + 9);
    const int a  = alias[b * SS + s];
    reinterpret_cast<float4*>(out)[tid] =
        reinterpret_cast<const float4*>(hfin)[((size_t)b * SS + a) * 32 + c4];
}

// ---------------------------------------------------------------
extern "C" void kernel_launch(void* const* d_in, const int* in_sizes, int n_in,
                              void* d_out, int out_size) {
    const float* hidden = (const float*)d_in[0];
    const float* adj    = (const float*)d_in[1];
    const int*   alias  = (const int*)d_in[2];
    const float* w1     = (const float*)d_in[3];
    const float* w2     = (const float*)d_in[4];
    const float* bias   = (const float*)d_in[5];
    float* out = (float*)d_out;

    cudaFuncSetAttribute(fused_layer_kernel,
                         cudaFuncAttributeMaxDynamicSharedMemorySize, SMEM_TOTAL);

    float* hb0;  cudaGetSymbolAddress((void**)&hb0, g_hbuf0);
    float* hb1;  cudaGetSymbolAddress((void**)&hb1, g_hbuf1);
    uint32_t* hhi; cudaGetSymbolAddress((void**)&hhi, g_hhi);
    uint32_t* hlo; cudaGetSymbolAddress((void**)&hlo, g_hlo);
    const size_t HC = (size_t)BB * SS * HH / 2;

    pack_code_kernel<<<dim3(SS / 32, SS / 32, BB), dim3(32, 32)>>>(adj);
    hsplit_kernel<<<(BB * SS * HH / 4) / 256, 256>>>(hidden, hhi, hlo);

    // layer 1: read split buf0 -> write hb0 fp32 + split buf1
    sasb_kernel<<<(BB * SS) / 8, 256>>>(hidden, w1, w2, bias);
    fused_layer_kernel<<<dim3(SS / 64, BB), 256, SMEM_TOTAL>>>(
        hhi, hlo, hb0, hhi + HC, hlo + HC, 1);

    // layer 2: read split buf1 -> fp32 out only
    sasb_kernel<<<(BB * SS) / 8, 256>>>(hb0, w1, w2, bias);
    fused_layer_kernel<<<dim3(SS / 64, BB), 256, SMEM_TOTAL>>>(
        hhi + HC, hlo + HC, hb1, hhi, hlo, 0);

    const int N4 = BB * SS * (HH / 4);
    gather_kernel<<<(N4 + 255) / 256, 256>>>(hb1, alias, out);
}

// round 8
// speedup vs baseline: 1.7472x; 1.0151x over previous
#include <cuda_runtime.h>
#include <cuda_bf16.h>
#include <cstdint>

typedef unsigned long long ull;

#define BB 128
#define SS 512
#define HH 128
#define EPSM 8.673617379884035e-19f   // 2^-60, exact in bf16

// -------- static device scratch --------
static __device__ unsigned char g_code[(size_t)BB * SS * SS];
static __device__ float g_hbuf0[(size_t)BB * SS * HH];
static __device__ float g_hbuf1[(size_t)BB * SS * HH];
static __device__ uint32_t g_hhi[2][(size_t)BB * SS * HH / 2];  // bf16x2 pairs
static __device__ uint32_t g_hlo[2][(size_t)BB * SS * HH / 2];
static __device__ float g_sa[BB * SS];
static __device__ float g_sb[BB * SS];

// ---------------- fast math ----------------
__device__ __forceinline__ float tanha(float x) {
    float r; asm("tanh.approx.f32 %0,%1;" : "=f"(r) : "f"(x)); return r;
}
__device__ __forceinline__ float ex2a(float x) {
    float r; asm("ex2.approx.f32 %0,%1;" : "=f"(r) : "f"(x)); return r;
}
__device__ __forceinline__ uint32_t bf2(float hi, float lo) {
    uint32_t r; asm("cvt.rn.bf16x2.f32 %0,%1,%2;" : "=r"(r) : "f"(hi), "f"(lo)); return r;
}

// ---------------- mma / ldsm / cp.async ----------------
__device__ __forceinline__ void ldsm_x4(uint32_t r[4], uint32_t addr) {
    asm volatile("ldmatrix.sync.aligned.m8n8.x4.shared.b16 {%0,%1,%2,%3}, [%4];"
        : "=r"(r[0]), "=r"(r[1]), "=r"(r[2]), "=r"(r[3]) : "r"(addr));
}
__device__ __forceinline__ void ldsm_x4_t(uint32_t r[4], uint32_t addr) {
    asm volatile("ldmatrix.sync.aligned.m8n8.x4.trans.shared.b16 {%0,%1,%2,%3}, [%4];"
        : "=r"(r[0]), "=r"(r[1]), "=r"(r[2]), "=r"(r[3]) : "r"(addr));
}
__device__ __forceinline__ void mma16816(float acc[4], const uint32_t a[4],
                                         uint32_t b0, uint32_t b1) {
    asm volatile(
        "mma.sync.aligned.m16n8k16.row.col.f32.bf16.bf16.f32 "
        "{%0,%1,%2,%3}, {%4,%5,%6,%7}, {%8,%9}, {%0,%1,%2,%3};\n"
        : "+f"(acc[0]), "+f"(acc[1]), "+f"(acc[2]), "+f"(acc[3])
        : "r"(a[0]), "r"(a[1]), "r"(a[2]), "r"(a[3]), "r"(b0), "r"(b1));
}
__device__ __forceinline__ void cp16(uint32_t dst, const void* src) {
    asm volatile("cp.async.cg.shared.global [%0], [%1], 16;" :: "r"(dst), "l"(src));
}
#define CP_COMMIT() asm volatile("cp.async.commit_group;" ::: "memory")
#define CP_WAIT0()  asm volatile("cp.async.wait_group 0;" ::: "memory")

// ---------------------------------------------------------------
// Kernel 1: symmetric pack, upper-triangular grid (136 tiles/batch)
// ---------------------------------------------------------------
#define NT (SS / 32)                 // 16
#define NPAIR (NT * (NT + 1) / 2)    // 136

__global__ void pack_code_kernel(const float* __restrict__ adj) {
    __shared__ float tA[32][33], tB[32][33];
    const int b = blockIdx.z;
    int rem = blockIdx.x;
    int It = 0;
    while (rem >= NT - It) { rem -= NT - It; It++; }
    const int I = It * 32;
    const int J = (It + rem) * 32;
    const int tx = threadIdx.x, ty = threadIdx.y;
    const float* A = adj + (size_t)b * SS * SS;

    tA[ty][tx] = A[(size_t)(I + ty) * SS + (J + tx)];
    tB[ty][tx] = A[(size_t)(J + ty) * SS + (I + tx)];
    __syncthreads();

    unsigned char cIJ = (tA[ty][tx] == 1.0f ? 1u : 0u) | (tB[tx][ty] == 1.0f ? 2u : 0u);
    unsigned char cJI = (tB[ty][tx] == 1.0f ? 1u : 0u) | (tA[tx][ty] == 1.0f ? 2u : 0u);
    g_code[((size_t)b * SS + (I + ty)) * SS + (J + tx)] = cIJ;
    g_code[((size_t)b * SS + (J + ty)) * SS + (I + tx)] = cJI;
}

// ---------------------------------------------------------------
// Kernel 2: sa = w1.h + bias, sb = w2.h, PLUS bf16 hi/lo split of h
// ---------------------------------------------------------------
__global__ void sasb_split_kernel(const float* __restrict__ hin,
                                  const float* __restrict__ w1,
                                  const float* __restrict__ w2,
                                  const float* __restrict__ bias_ptr,
                                  uint32_t* __restrict__ hi_out,
                                  uint32_t* __restrict__ lo_out) {
    const int tid  = threadIdx.x;
    const int lane = tid & 31;
    const int row  = blockIdx.x * 8 + (tid >> 5);
    if (row >= BB * SS) return;

    const float4 hv  = reinterpret_cast<const float4*>(hin)[(size_t)row * 32 + lane];
    const float4 w1v = reinterpret_cast<const float4*>(w1)[lane];
    const float4 w2v = reinterpret_cast<const float4*>(w2)[lane];

    // bf16 hi/lo split store
    {
        const uint32_t h01 = bf2(hv.y, hv.x);
        const uint32_t h23 = bf2(hv.w, hv.z);
        const float l0 = hv.x - __uint_as_float(h01 << 16);
        const float l1 = hv.y - __uint_as_float(h01 & 0xFFFF0000u);
        const float l2 = hv.z - __uint_as_float(h23 << 16);
        const float l3 = hv.w - __uint_as_float(h23 & 0xFFFF0000u);
        reinterpret_cast<uint2*>(hi_out)[(size_t)row * 32 + lane] = make_uint2(h01, h23);
        reinterpret_cast<uint2*>(lo_out)[(size_t)row * 32 + lane] =
            make_uint2(bf2(l1, l0), bf2(l3, l2));
    }

    float d1 = hv.x * w1v.x + hv.y * w1v.y + hv.z * w1v.z + hv.w * w1v.w;
    float d2 = hv.x * w2v.x + hv.y * w2v.y + hv.z * w2v.z + hv.w * w2v.w;
    #pragma unroll
    for (int off = 16; off > 0; off >>= 1) {
        d1 += __shfl_xor_sync(0xFFFFFFFFu, d1, off);
        d2 += __shfl_xor_sync(0xFFFFFFFFu, d2, off);
    }
    if (lane == 0) {
        g_sa[row] = d1 + bias_ptr[0];
        g_sb[row] = d2;
    }
}

// ---------------------------------------------------------------
// score quad (MUFU): 4 elems -> bf16 hi/lo pairs + partial sum
// ---------------------------------------------------------------
#define HLOG2E 0.721347520444f   // 0.5 * log2(e)

__device__ __forceinline__ float quad4(uint32_t c4, const float4 sa4, const float4 sb4,
                                       const float sai, const float sbi,
                                       uint32_t& h01, uint32_t& h23,
                                       uint32_t& l01, uint32_t& l23) {
    float t1[4], t2[4];
    t1[0] = tanha(sai + sb4.x);  t1[1] = tanha(sai + sb4.y);
    t1[2] = tanha(sai + sb4.z);  t1[3] = tanha(sai + sb4.w);
    t2[0] = tanha(sa4.x + sbi);  t2[1] = tanha(sa4.y + sbi);
    t2[2] = tanha(sa4.z + sbi);  t2[3] = tanha(sa4.w + sbi);
    float e[4]; float es = 0.0f;
    #pragma unroll
    for (int k = 0; k < 4; k++) {
        const uint32_t c = (c4 >> (8 * k)) & 0xFFu;
        const float f1 = (c & 1u) ? t1[k] : 0.0f;
        const float f2 = (c & 2u) ? t2[k] : 0.0f;
        const float ev = ex2a((f1 + f2) * HLOG2E);
        e[k] = c ? ev : EPSM;
        es += e[k];
    }
    h01 = bf2(e[1], e[0]);
    h23 = bf2(e[3], e[2]);
    const float l0 = e[0] - __uint_as_float(h01 << 16);
    const float l1 = e[1] - __uint_as_float(h01 & 0xFFFF0000u);
    const float l2 = e[2] - __uint_as_float(h23 << 16);
    const float l3 = e[3] - __uint_as_float(h23 & 0xFFFF0000u);
    l01 = bf2(l1, l0);
    l23 = bf2(l3, l2);
    return es;
}

// ---------------------------------------------------------------
// Kernel 3: fused. 64 rows/block, 256 thr, DOUBLE-buffered P and H,
// ONE barrier per chunk: prefetch H(kc+1) | MMA(kc) | E(kc+1) | sync.
// smem 107008 B -> 2 blocks/SM.
// ---------------------------------------------------------------
#define OFF_SA   0
#define OFF_SB   2048
#define OFF_RS   4096
#define OFF_P    4608
#define P_PART   8192
#define P_BUFSZ  16384
#define OFF_H    37376
#define H_PART   17408
#define H_BUFSZ  34816
#define SMEM_TOTAL 107008
#define LDHB 272

__global__ __launch_bounds__(256, 2)
void fused_layer_kernel(const uint32_t* __restrict__ hhi_in,
                        const uint32_t* __restrict__ hlo_in,
                        float* __restrict__ hout,
                        uint32_t* __restrict__ hhi_out,
                        uint32_t* __restrict__ hlo_out,
                        int write_split) {
    extern __shared__ char smem[];
    float* s_sa   = (float*)(smem + OFF_SA);
    float* s_sb   = (float*)(smem + OFF_SB);
    float* s_rsum = (float*)(smem + OFF_RS);
    const uint32_t su = (uint32_t)__cvta_generic_to_shared(smem);

    const int b    = blockIdx.y;
    const int i0   = blockIdx.x * 64;
    const int tid  = threadIdx.x;
    const int lane = tid & 31;
    const int w    = tid >> 5;

    #pragma unroll
    for (int q = 0; q < 2; q++) {
        int j = q * 256 + tid;
        s_sa[j] = g_sa[b * SS + j];
        s_sb[j] = g_sb[b * SS + j];
    }

    const uint32_t* hhiB = hhi_in + (size_t)b * SS * (HH / 2);
    const uint32_t* hloB = hlo_in + (size_t)b * SS * (HH / 2);

    // prefetch H chunk 0 -> buf 0
    #pragma unroll
    for (int t = 0; t < 4; t++) {
        const int idx = t * 256 + tid;
        const int k = idx >> 4, g = idx & 15;
        const uint32_t d = su + OFF_H + k * LDHB + g * 16;
        cp16(d,          hhiB + (size_t)k * 64 + g * 4);
        cp16(d + H_PART, hloB + (size_t)k * 64 + g * 4);
    }
    CP_COMMIT();
    __syncthreads();   // sa/sb visible

    // Phase-E constants: 4 threads/row
    const int er = tid >> 2;
    const int eq = tid & 3;
    const float sai = s_sa[i0 + er];
    const float sbi = s_sb[i0 + er];
    const unsigned char* crow = g_code + ((size_t)b * SS + i0 + er) * SS;
    float esum = 0.0f;

    // E for chunk kc into P buf (kc&1)
    auto e_chunk = [&](int kc) {
        char* ph = smem + OFF_P + (kc & 1) * P_BUFSZ + er * 128;
        char* pl = ph + P_PART;
        #pragma unroll
        for (int sh = 0; sh < 2; sh++) {
            const int seg = eq + sh * 4;            // 16B unit 0..7
            const int j0 = kc * 64 + seg * 8;
            const ull codes = *(const ull*)(crow + j0);
            const float4 sb0 = *(const float4*)(s_sb + j0);
            const float4 sb1 = *(const float4*)(s_sb + j0 + 4);
            const float4 sa0 = *(const float4*)(s_sa + j0);
            const float4 sa1 = *(const float4*)(s_sa + j0 + 4);
            uint32_t h0, h1, h2, h3, l0, l1, l2, l3;
            esum += quad4((uint32_t)codes,         sa0, sb0, sai, sbi, h0, h1, l0, l1);
            esum += quad4((uint32_t)(codes >> 32), sa1, sb1, sai, sbi, h2, h3, l2, l3);
            const uint32_t phys = ((uint32_t)(seg ^ (er & 7))) * 16u;
            *(uint4*)(ph + phys) = make_uint4(h0, h1, h2, h3);
            *(uint4*)(pl + phys) = make_uint4(l0, l1, l2, l3);
        }
    };

    // E(0) -> P buf 0, then wait H(0)
    e_chunk(0);
    CP_WAIT0();
    __syncthreads();

    // MMA constants (proven fragment mapping)
    const int mi = w & 3;
    const int ni = w >> 2;
    const int m0 = mi * 16;
    const int arow = m0 + (lane & 15);
    const int aunit0 = (lane >> 4);
    const int brow = (lane & 7) + ((lane >> 3) & 1) * 8;
    const uint32_t b_cb = (uint32_t)((ni * 64 + (lane >> 4) * 8) * 2);

    float acc[8][4];
    #pragma unroll
    for (int nf = 0; nf < 8; nf++)
        #pragma unroll
        for (int q = 0; q < 4; q++) acc[nf][q] = 0.0f;

    for (int kc = 0; kc < 8; kc++) {
        // prefetch H(kc+1) into the other buffer (its last reader was MMA(kc-1))
        if (kc < 7) {
            const int nb = (kc + 1) & 1;
            #pragma unroll
            for (int t = 0; t < 4; t++) {
                const int idx = t * 256 + tid;
                const int k = idx >> 4, g = idx & 15;
                const uint32_t d = su + OFF_H + nb * H_BUFSZ + k * LDHB + g * 16;
                const size_t src = (size_t)((kc + 1) * 64 + k) * 64 + g * 4;
                cp16(d,          hhiB + src);
                cp16(d + H_PART, hloB + src);
            }
            CP_COMMIT();
        }

        // MMA on chunk kc (P[kc&1], H[kc&1]); E(kc+1) issues in the same window
        {
            const uint32_t pb = su + OFF_P + (kc & 1) * P_BUFSZ + arow * 128;
            const uint32_t hb = su + OFF_H + (kc & 1) * H_BUFSZ;
            #pragma unroll
            for (int s = 0; s < 4; s++) {
                const uint32_t phys = (((uint32_t)(s * 2 + aunit0)) ^ (uint32_t)(arow & 7)) * 16u;
                uint32_t ahi[4], alo[4];
                ldsm_x4(ahi, pb + phys);
                ldsm_x4(alo, pb + P_PART + phys);
                #pragma unroll
                for (int nn = 0; nn < 4; nn++) {
                    const uint32_t baddr = hb + (uint32_t)((s * 16 + brow) * LDHB)
                                         + b_cb + (uint32_t)(nn * 32);
                    uint32_t bh[4], bl[4];
                    ldsm_x4_t(bh, baddr);
                    ldsm_x4_t(bl, baddr + H_PART);
                    mma16816(acc[2 * nn],     ahi, bh[0], bh[1]);
                    mma16816(acc[2 * nn],     ahi, bl[0], bl[1]);
                    mma16816(acc[2 * nn],     alo, bh[0], bh[1]);
                    mma16816(acc[2 * nn + 1], ahi, bh[2], bh[3]);
                    mma16816(acc[2 * nn + 1], ahi, bl[2], bl[3]);
                    mma16816(acc[2 * nn + 1], alo, bh[2], bh[3]);
                }
            }
        }

        if (kc < 7) {
            e_chunk(kc + 1);   // writes P[(kc+1)&1]; last reader MMA(kc-1) done pre-barrier
            CP_WAIT0();        // H(kc+1) landed
        }
        __syncthreads();       // P/H(kc+1) visible; MMA(kc) reads complete
    }

    // row sums
    esum += __shfl_xor_sync(0xFFFFFFFFu, esum, 1);
    esum += __shfl_xor_sync(0xFFFFFFFFu, esum, 2);
    if (eq == 0) s_rsum[er] = esum;
    __syncthreads();

    // epilogue: normalize, store fp32 (+ bf16 hi/lo split for next layer)
    const int r0 = m0 + (lane >> 2);
    const float inv0 = 1.0f / s_rsum[r0];
    const float inv1 = 1.0f / s_rsum[r0 + 8];
    const size_t gr0 = ((size_t)b * SS + i0 + r0) * HH;
    const size_t gr1 = gr0 + 8 * HH;
    #pragma unroll
    for (int nf = 0; nf < 8; nf++) {
        const int col = ni * 64 + nf * 8 + 2 * (lane & 3);
        const float v0 = acc[nf][0] * inv0, v1 = acc[nf][1] * inv0;
        const float v2 = acc[nf][2] * inv1, v3 = acc[nf][3] * inv1;
        *(float2*)(hout + gr0 + col) = make_float2(v0, v1);
        *(float2*)(hout + gr1 + col) = make_float2(v2, v3);

        if (write_split) {
            uint32_t hp0 = bf2(v1, v0);
            uint32_t hp1 = bf2(v3, v2);
            const float a0 = v0 - __uint_as_float(hp0 << 16);
            const float a1 = v1 - __uint_as_float(hp0 & 0xFFFF0000u);
            const float a2 = v2 - __uint_as_float(hp1 << 16);
            const float a3 = v3 - __uint_as_float(hp1 & 0xFFFF0000u);
            hhi_out[(gr0 + col) >> 1] = hp0;
            hlo_out[(gr0 + col) >> 1] = bf2(a1, a0);
            hhi_out[(gr1 + col) >> 1] = hp1;
            hlo_out[(gr1 + col) >> 1] = bf2(a3, a2);
        }
    }
}

// ---------------------------------------------------------------
// Kernel 4: gather rows by alias_inputs
// ---------------------------------------------------------------
__global__ void gather_kernel(const float* __restrict__ hfin,
                              const int* __restrict__ alias,
                              float* __restrict__ out) {
    const int tid = blockIdx.x * blockDim.x + threadIdx.x;
    const int N4 = BB * SS * (HH / 4);
    if (tid >= N4) return;
    const int c4 = tid & 31;
    const int s  = (tid >> 5) & (SS - 1);
    const int b  = tid >> (5 + 9);
    const int a  = alias[b * SS + s];
    reinterpret_cast<float4*>(out)[tid] =
        reinterpret_cast<const float4*>(hfin)[((size_t)b * SS + a) * 32 + c4];
}

// ---------------------------------------------------------------
extern "C" void kernel_launch(void* const* d_in, const int* in_sizes, int n_in,
                              void* d_out, int out_size) {
    const float* hidden = (const float*)d_in[0];
    const float* adj    = (const float*)d_in[1];
    const int*   alias  = (const int*)d_in[2];
    const float* w1     = (const float*)d_in[3];
    const float* w2     = (const float*)d_in[4];
    const float* bias   = (const float*)d_in[5];
    float* out = (float*)d_out;

    cudaFuncSetAttribute(fused_layer_kernel,
                         cudaFuncAttributeMaxDynamicSharedMemorySize, SMEM_TOTAL);

    float* hb0;  cudaGetSymbolAddress((void**)&hb0, g_hbuf0);
    float* hb1;  cudaGetSymbolAddress((void**)&hb1, g_hbuf1);
    uint32_t* hhi; cudaGetSymbolAddress((void**)&hhi, g_hhi);
    uint32_t* hlo; cudaGetSymbolAddress((void**)&hlo, g_hlo);
    const size_t HC = (size_t)BB * SS * HH / 2;

    pack_code_kernel<<<dim3(NPAIR, 1, BB), dim3(32, 32)>>>(adj);

    // layer 1: sasb + split of input hidden -> buf0
    sasb_split_kernel<<<(BB * SS) / 8, 256>>>(hidden, w1, w2, bias, hhi, hlo);
    fused_layer_kernel<<<dim3(SS / 64, BB), 256, SMEM_TOTAL>>>(
        hhi, hlo, hb0, hhi + HC, hlo + HC, 1);

    // layer 2: sasb on hb0 (split buf1 already written by layer-1 epilogue)
    sasb_split_kernel<<<(BB * SS) / 8, 256>>>(hb0, w1, w2, bias, hhi, hlo);
    fused_layer_kernel<<<dim3(SS / 64, BB), 256, SMEM_TOTAL>>>(
        hhi + HC, hlo + HC, hb1, hhi, hlo, 0);

    const int N4 = BB * SS * (HH / 4);
    gather_kernel<<<(N4 + 255) / 256, 256>>>(hb1, alias, out);
}

// round 9
// speedup vs baseline: 1.8592x; 1.0641x over previous
#include <cuda_runtime.h>
#include <cuda_bf16.h>
#include <cstdint>

typedef unsigned long long ull;

#define BB 128
#define SS 512
#define HH 128
#define EPSM 8.673617379884035e-19f   // 2^-60, exact in bf16

// -------- static device scratch --------
static __device__ unsigned char g_code[(size_t)BB * SS * SS];
static __device__ float g_hbuf0[(size_t)BB * SS * HH];
static __device__ float g_hbuf1[(size_t)BB * SS * HH];
static __device__ uint32_t g_hhi[2][(size_t)BB * SS * HH / 2];  // bf16x2 pairs
static __device__ uint32_t g_hlo[2][(size_t)BB * SS * HH / 2];
static __device__ float g_sa[BB * SS];
static __device__ float g_sb[BB * SS];

// ---------------- fast math ----------------
__device__ __forceinline__ float tanha(float x) {
    float r; asm("tanh.approx.f32 %0,%1;" : "=f"(r) : "f"(x)); return r;
}
__device__ __forceinline__ float ex2a(float x) {
    float r; asm("ex2.approx.f32 %0,%1;" : "=f"(r) : "f"(x)); return r;
}
__device__ __forceinline__ uint32_t bf2(float hi, float lo) {
    uint32_t r; asm("cvt.rn.bf16x2.f32 %0,%1,%2;" : "=r"(r) : "f"(hi), "f"(lo)); return r;
}

// ---------------- mma / ldsm / cp.async / named barriers ----------------
__device__ __forceinline__ void ldsm_x4(uint32_t r[4], uint32_t addr) {
    asm volatile("ldmatrix.sync.aligned.m8n8.x4.shared.b16 {%0,%1,%2,%3}, [%4];"
        : "=r"(r[0]), "=r"(r[1]), "=r"(r[2]), "=r"(r[3]) : "r"(addr));
}
__device__ __forceinline__ void ldsm_x4_t(uint32_t r[4], uint32_t addr) {
    asm volatile("ldmatrix.sync.aligned.m8n8.x4.trans.shared.b16 {%0,%1,%2,%3}, [%4];"
        : "=r"(r[0]), "=r"(r[1]), "=r"(r[2]), "=r"(r[3]) : "r"(addr));
}
__device__ __forceinline__ void mma16816(float acc[4], const uint32_t a[4],
                                         uint32_t b0, uint32_t b1) {
    asm volatile(
        "mma.sync.aligned.m16n8k16.row.col.f32.bf16.bf16.f32 "
        "{%0,%1,%2,%3}, {%4,%5,%6,%7}, {%8,%9}, {%0,%1,%2,%3};\n"
        : "+f"(acc[0]), "+f"(acc[1]), "+f"(acc[2]), "+f"(acc[3])
        : "r"(a[0]), "r"(a[1]), "r"(a[2]), "r"(a[3]), "r"(b0), "r"(b1));
}
__device__ __forceinline__ void cp16(uint32_t dst, const void* src) {
    asm volatile("cp.async.cg.shared.global [%0], [%1], 16;" :: "r"(dst), "l"(src));
}
#define CP_COMMIT() asm volatile("cp.async.commit_group;" ::: "memory")
#define CP_WAIT0()  asm volatile("cp.async.wait_group 0;" ::: "memory")
#define BAR_SYNC(id)   asm volatile("bar.sync %0, 256;"   :: "r"(id) : "memory")
#define BAR_ARRIVE(id) asm volatile("bar.arrive %0, 256;" :: "r"(id) : "memory")

// ---------------------------------------------------------------
// Kernel 1: symmetric pack, upper-triangular grid
// ---------------------------------------------------------------
#define NT (SS / 32)
#define NPAIR (NT * (NT + 1) / 2)

__global__ void pack_code_kernel(const float* __restrict__ adj) {
    __shared__ float tA[32][33], tB[32][33];
    const int b = blockIdx.z;
    int rem = blockIdx.x;
    int It = 0;
    while (rem >= NT - It) { rem -= NT - It; It++; }
    const int I = It * 32;
    const int J = (It + rem) * 32;
    const int tx = threadIdx.x, ty = threadIdx.y;
    const float* A = adj + (size_t)b * SS * SS;

    tA[ty][tx] = A[(size_t)(I + ty) * SS + (J + tx)];
    tB[ty][tx] = A[(size_t)(J + ty) * SS + (I + tx)];
    __syncthreads();

    unsigned char cIJ = (tA[ty][tx] == 1.0f ? 1u : 0u) | (tB[tx][ty] == 1.0f ? 2u : 0u);
    unsigned char cJI = (tB[ty][tx] == 1.0f ? 1u : 0u) | (tA[tx][ty] == 1.0f ? 2u : 0u);
    g_code[((size_t)b * SS + (I + ty)) * SS + (J + tx)] = cIJ;
    g_code[((size_t)b * SS + (J + ty)) * SS + (I + tx)] = cJI;
}

// ---------------------------------------------------------------
// Kernel 2: sa/sb projections + bf16 hi/lo split of h
// ---------------------------------------------------------------
__global__ void sasb_split_kernel(const float* __restrict__ hin,
                                  const float* __restrict__ w1,
                                  const float* __restrict__ w2,
                                  const float* __restrict__ bias_ptr,
                                  uint32_t* __restrict__ hi_out,
                                  uint32_t* __restrict__ lo_out) {
    const int tid  = threadIdx.x;
    const int lane = tid & 31;
    const int row  = blockIdx.x * 8 + (tid >> 5);
    if (row >= BB * SS) return;

    const float4 hv  = reinterpret_cast<const float4*>(hin)[(size_t)row * 32 + lane];
    const float4 w1v = reinterpret_cast<const float4*>(w1)[lane];
    const float4 w2v = reinterpret_cast<const float4*>(w2)[lane];

    {
        const uint32_t h01 = bf2(hv.y, hv.x);
        const uint32_t h23 = bf2(hv.w, hv.z);
        const float l0 = hv.x - __uint_as_float(h01 << 16);
        const float l1 = hv.y - __uint_as_float(h01 & 0xFFFF0000u);
        const float l2 = hv.z - __uint_as_float(h23 << 16);
        const float l3 = hv.w - __uint_as_float(h23 & 0xFFFF0000u);
        reinterpret_cast<uint2*>(hi_out)[(size_t)row * 32 + lane] = make_uint2(h01, h23);
        reinterpret_cast<uint2*>(lo_out)[(size_t)row * 32 + lane] =
            make_uint2(bf2(l1, l0), bf2(l3, l2));
    }

    float d1 = hv.x * w1v.x + hv.y * w1v.y + hv.z * w1v.z + hv.w * w1v.w;
    float d2 = hv.x * w2v.x + hv.y * w2v.y + hv.z * w2v.z + hv.w * w2v.w;
    #pragma unroll
    for (int off = 16; off > 0; off >>= 1) {
        d1 += __shfl_xor_sync(0xFFFFFFFFu, d1, off);
        d2 += __shfl_xor_sync(0xFFFFFFFFu, d2, off);
    }
    if (lane == 0) {
        g_sa[row] = d1 + bias_ptr[0];
        g_sb[row] = d2;
    }
}

// ---------------------------------------------------------------
// score quad (MUFU)
// ---------------------------------------------------------------
#define HLOG2E 0.721347520444f

__device__ __forceinline__ float quad4(uint32_t c4, const float4 sa4, const float4 sb4,
                                       const float sai, const float sbi,
                                       uint32_t& h01, uint32_t& h23,
                                       uint32_t& l01, uint32_t& l23) {
    float t1[4], t2[4];
    t1[0] = tanha(sai + sb4.x);  t1[1] = tanha(sai + sb4.y);
    t1[2] = tanha(sai + sb4.z);  t1[3] = tanha(sai + sb4.w);
    t2[0] = tanha(sa4.x + sbi);  t2[1] = tanha(sa4.y + sbi);
    t2[2] = tanha(sa4.z + sbi);  t2[3] = tanha(sa4.w + sbi);
    float e[4]; float es = 0.0f;
    #pragma unroll
    for (int k = 0; k < 4; k++) {
        const uint32_t c = (c4 >> (8 * k)) & 0xFFu;
        const float f1 = (c & 1u) ? t1[k] : 0.0f;
        const float f2 = (c & 2u) ? t2[k] : 0.0f;
        const float ev = ex2a((f1 + f2) * HLOG2E);
        e[k] = c ? ev : EPSM;
        es += e[k];
    }
    h01 = bf2(e[1], e[0]);
    h23 = bf2(e[3], e[2]);
    const float l0 = e[0] - __uint_as_float(h01 << 16);
    const float l1 = e[1] - __uint_as_float(h01 & 0xFFFF0000u);
    const float l2 = e[2] - __uint_as_float(h23 << 16);
    const float l3 = e[3] - __uint_as_float(h23 & 0xFFFF0000u);
    l01 = bf2(l1, l0);
    l23 = bf2(l3, l2);
    return es;
}

// ---------------------------------------------------------------
// Kernel 3: WARP-SPECIALIZED fused kernel. 64 rows/block, 256 thr.
// Warps 0-3: MMA consumers (16 rows x 128 cols each).
// Warps 4-7: E producers (2 thr/row) + H cp.async.
// Named barriers: full[b]=1+b, empty[b]=3+b, final=5.
// ---------------------------------------------------------------
#define OFF_SA   0
#define OFF_SB   2048
#define OFF_RS   4096
#define OFF_P    4608
#define P_PART   8192
#define P_BUFSZ  16384
#define OFF_H    37376
#define H_PART   17408
#define H_BUFSZ  34816
#define SMEM_TOTAL 107008
#define LDHB 272

__global__ __launch_bounds__(256, 2)
void fused_layer_kernel(const uint32_t* __restrict__ hhi_in,
                        const uint32_t* __restrict__ hlo_in,
                        float* __restrict__ hout,
                        uint32_t* __restrict__ hhi_out,
                        uint32_t* __restrict__ hlo_out,
                        int write_split) {
    extern __shared__ char smem[];
    float* s_sa   = (float*)(smem + OFF_SA);
    float* s_sb   = (float*)(smem + OFF_SB);
    float* s_rsum = (float*)(smem + OFF_RS);
    const uint32_t su = (uint32_t)__cvta_generic_to_shared(smem);

    const int b    = blockIdx.y;
    const int i0   = blockIdx.x * 64;
    const int tid  = threadIdx.x;
    const int lane = tid & 31;
    const int w    = tid >> 5;

    #pragma unroll
    for (int q = 0; q < 2; q++) {
        int j = q * 256 + tid;
        s_sa[j] = g_sa[b * SS + j];
        s_sb[j] = g_sb[b * SS + j];
    }
    __syncthreads();

    if (w >= 4) {
        // =================== PRODUCER: E + H staging ===================
        const int et = tid - 128;
        const int er = et >> 1;             // row 0..63
        const int eq = et & 1;
        const float sai = s_sa[i0 + er];
        const float sbi = s_sb[i0 + er];
        const unsigned char* crow = g_code + ((size_t)b * SS + i0 + er) * SS;
        const uint32_t* hhiB = hhi_in + (size_t)b * SS * (HH / 2);
        const uint32_t* hloB = hlo_in + (size_t)b * SS * (HH / 2);
        float esum = 0.0f;

        for (int kc = 0; kc < 8; kc++) {
            const int buf = kc & 1;
            if (kc >= 2) BAR_SYNC(3 + buf);          // MMA done with this buf

            // stage H(kc) -> H buf
            {
                const uint32_t hb = su + OFF_H + buf * H_BUFSZ;
                #pragma unroll
                for (int t = 0; t < 8; t++) {
                    const int idx = t * 128 + et;
                    const int k = idx >> 4, g = idx & 15;
                    const uint32_t d = hb + k * LDHB + g * 16;
                    const size_t src = (size_t)(kc * 64 + k) * 64 + g * 4;
                    cp16(d,          hhiB + src);
                    cp16(d + H_PART, hloB + src);
                }
                CP_COMMIT();
            }

            // compute E(kc) -> P buf
            {
                char* ph = smem + OFF_P + buf * P_BUFSZ + er * 128;
                char* pl = ph + P_PART;
                #pragma unroll
                for (int u = 0; u < 4; u++) {
                    const int seg = eq * 4 + u;      // 16B unit 0..7
                    const int j0 = kc * 64 + seg * 8;
                    const ull codes = *(const ull*)(crow + j0);
                    const float4 sb0 = *(const float4*)(s_sb + j0);
                    const float4 sb1 = *(const float4*)(s_sb + j0 + 4);
                    const float4 sa0 = *(const float4*)(s_sa + j0);
                    const float4 sa1 = *(const float4*)(s_sa + j0 + 4);
                    uint32_t h0, h1, h2, h3, l0, l1, l2, l3;
                    esum += quad4((uint32_t)codes,         sa0, sb0, sai, sbi, h0, h1, l0, l1);
                    esum += quad4((uint32_t)(codes >> 32), sa1, sb1, sai, sbi, h2, h3, l2, l3);
                    const uint32_t phys = ((uint32_t)(seg ^ (er & 7))) * 16u;
                    *(uint4*)(ph + phys) = make_uint4(h0, h1, h2, h3);
                    *(uint4*)(pl + phys) = make_uint4(l0, l1, l2, l3);
                }
            }

            CP_WAIT0();                              // H(kc) landed
            BAR_ARRIVE(1 + buf);                     // publish P(kc)+H(kc)
        }

        // row sums (partner = adjacent lane)
        esum += __shfl_xor_sync(0xFFFFFFFFu, esum, 1);
        if (eq == 0) s_rsum[er] = esum;
        BAR_SYNC(5);
        // producers done
    } else {
        // =================== CONSUMER: MMA + epilogue ===================
        const int m0 = w * 16;
        const int arow = m0 + (lane & 15);
        const int aunit0 = (lane >> 4);
        const int brow = (lane & 7) + ((lane >> 3) & 1) * 8;
        const uint32_t b_cb0 = (uint32_t)(((lane >> 4) * 8) * 2);

        float acc[16][4];
        #pragma unroll
        for (int nf = 0; nf < 16; nf++)
            #pragma unroll
            for (int q = 0; q < 4; q++) acc[nf][q] = 0.0f;

        for (int kc = 0; kc < 8; kc++) {
            const int buf = kc & 1;
            BAR_SYNC(1 + buf);                       // wait P(kc)+H(kc)

            const uint32_t pb = su + OFF_P + buf * P_BUFSZ + arow * 128;
            const uint32_t hb = su + OFF_H + buf * H_BUFSZ;
            #pragma unroll
            for (int s = 0; s < 4; s++) {
                const uint32_t phys = (((uint32_t)(s * 2 + aunit0)) ^ (uint32_t)(arow & 7)) * 16u;
                uint32_t ahi[4], alo[4];
                ldsm_x4(ahi, pb + phys);
                ldsm_x4(alo, pb + P_PART + phys);
                const uint32_t brbase = hb + (uint32_t)((s * 16 + brow) * LDHB) + b_cb0;
                #pragma unroll
                for (int nn = 0; nn < 8; nn++) {
                    const uint32_t baddr = brbase + (uint32_t)(nn * 32);
                    uint32_t bh[4], bl[4];
                    ldsm_x4_t(bh, baddr);
                    ldsm_x4_t(bl, baddr + H_PART);
                    mma16816(acc[2 * nn],     ahi, bh[0], bh[1]);
                    mma16816(acc[2 * nn],     ahi, bl[0], bl[1]);
                    mma16816(acc[2 * nn],     alo, bh[0], bh[1]);
                    mma16816(acc[2 * nn + 1], ahi, bh[2], bh[3]);
                    mma16816(acc[2 * nn + 1], ahi, bl[2], bl[3]);
                    mma16816(acc[2 * nn + 1], alo, bh[2], bh[3]);
                }
            }

            if (kc < 6) BAR_ARRIVE(3 + buf);         // release buf for E(kc+2)
        }

        BAR_SYNC(5);                                 // rsum ready

        // epilogue: normalize, store fp32 (+ split)
        const int r0 = m0 + (lane >> 2);
        const float inv0 = 1.0f / s_rsum[r0];
        const float inv1 = 1.0f / s_rsum[r0 + 8];
        const size_t gr0 = ((size_t)b * SS + i0 + r0) * HH;
        const size_t gr1 = gr0 + 8 * HH;
        #pragma unroll
        for (int nf = 0; nf < 16; nf++) {
            const int col = nf * 8 + 2 * (lane & 3);
            const float v0 = acc[nf][0] * inv0, v1 = acc[nf][1] * inv0;
            const float v2 = acc[nf][2] * inv1, v3 = acc[nf][3] * inv1;
            *(float2*)(hout + gr0 + col) = make_float2(v0, v1);
            *(float2*)(hout + gr1 + col) = make_float2(v2, v3);

            if (write_split) {
                uint32_t hp0 = bf2(v1, v0);
                uint32_t hp1 = bf2(v3, v2);
                const float a0 = v0 - __uint_as_float(hp0 << 16);
                const float a1 = v1 - __uint_as_float(hp0 & 0xFFFF0000u);
                const float a2 = v2 - __uint_as_float(hp1 << 16);
                const float a3 = v3 - __uint_as_float(hp1 & 0xFFFF0000u);
                hhi_out[(gr0 + col) >> 1] = hp0;
                hlo_out[(gr0 + col) >> 1] = bf2(a1, a0);
                hhi_out[(gr1 + col) >> 1] = hp1;
                hlo_out[(gr1 + col) >> 1] = bf2(a3, a2);
            }
        }
    }
}

// ---------------------------------------------------------------
// Kernel 4: gather rows by alias_inputs
// ---------------------------------------------------------------
__global__ void gather_kernel(const float* __restrict__ hfin,
                              const int* __restrict__ alias,
                              float* __restrict__ out) {
    const int tid = blockIdx.x * blockDim.x + threadIdx.x;
    const int N4 = BB * SS * (HH / 4);
    if (tid >= N4) return;
    const int c4 = tid & 31;
    const int s  = (tid >> 5) & (SS - 1);
    const int b  = tid >> (5 + 9);
    const int a  = alias[b * SS + s];
    reinterpret_cast<float4*>(out)[tid] =
        reinterpret_cast<const float4*>(hfin)[((size_t)b * SS + a) * 32 + c4];
}

// ---------------------------------------------------------------
extern "C" void kernel_launch(void* const* d_in, const int* in_sizes, int n_in,
                              void* d_out, int out_size) {
    const float* hidden = (const float*)d_in[0];
    const float* adj    = (const float*)d_in[1];
    const int*   alias  = (const int*)d_in[2];
    const float* w1     = (const float*)d_in[3];
    const float* w2     = (const float*)d_in[4];
    const float* bias   = (const float*)d_in[5];
    float* out = (float*)d_out;

    cudaFuncSetAttribute(fused_layer_kernel,
                         cudaFuncAttributeMaxDynamicSharedMemorySize, SMEM_TOTAL);

    float* hb0;  cudaGetSymbolAddress((void**)&hb0, g_hbuf0);
    float* hb1;  cudaGetSymbolAddress((void**)&hb1, g_hbuf1);
    uint32_t* hhi; cudaGetSymbolAddress((void**)&hhi, g_hhi);
    uint32_t* hlo; cudaGetSymbolAddress((void**)&hlo, g_hlo);
    const size_t HC = (size_t)BB * SS * HH / 2;

    pack_code_kernel<<<dim3(NPAIR, 1, BB), dim3(32, 32)>>>(adj);

    sasb_split_kernel<<<(BB * SS) / 8, 256>>>(hidden, w1, w2, bias, hhi, hlo);
    fused_layer_kernel<<<dim3(SS / 64, BB), 256, SMEM_TOTAL>>>(
        hhi, hlo, hb0, hhi + HC, hlo + HC, 1);

    sasb_split_kernel<<<(BB * SS) / 8, 256>>>(hb0, w1, w2, bias, hhi, hlo);
    fused_layer_kernel<<<dim3(SS / 64, BB), 256, SMEM_TOTAL>>>(
        hhi + HC, hlo + HC, hb1, hhi, hlo, 0);

    const int N4 = BB * SS * (HH / 4);
    gather_kernel<<<(N4 + 255) / 256, 256>>>(hb1, alias, out);
}

// round 10
// speedup vs baseline: 1.9473x; 1.0474x over previous
#include <cuda_runtime.h>
#include <cuda_bf16.h>
#include <cuda_fp16.h>
#include <cstdint>

typedef unsigned long long ull;

#define BB 128
#define SS 512
#define HH 128
#define EPSM 5.9604644775390625e-08f   // 2^-24, exact fp16 subnormal

// -------- static device scratch --------
static __device__ unsigned char g_code[(size_t)BB * SS * SS];
static __device__ float g_hbuf0[(size_t)BB * SS * HH];
static __device__ float g_hbuf1[(size_t)BB * SS * HH];
static __device__ uint32_t g_hhi[2][(size_t)BB * SS * HH / 2];  // f16x2 pairs
static __device__ uint32_t g_hlo[2][(size_t)BB * SS * HH / 2];
static __device__ float g_sa[BB * SS];
static __device__ float g_sb[BB * SS];

// ---------------- fast math ----------------
__device__ __forceinline__ float tanha(float x) {
    float r; asm("tanh.approx.f32 %0,%1;" : "=f"(r) : "f"(x)); return r;
}
__device__ __forceinline__ float ex2a(float x) {
    float r; asm("ex2.approx.f32 %0,%1;" : "=f"(r) : "f"(x)); return r;
}
// pack two f32 -> f16x2 (high = first arg, low = second arg)
__device__ __forceinline__ uint32_t f2h2(float hi, float lo) {
    uint32_t r; asm("cvt.rn.f16x2.f32 %0,%1,%2;" : "=r"(r) : "f"(hi), "f"(lo)); return r;
}
__device__ __forceinline__ float hlo2f(uint32_t p) {
    float f; asm("{.reg .b16 l,h; mov.b32 {l,h},%1; cvt.f32.f16 %0,l;}" : "=f"(f) : "r"(p));
    return f;
}
__device__ __forceinline__ float hhi2f(uint32_t p) {
    float f; asm("{.reg .b16 l,h; mov.b32 {l,h},%1; cvt.f32.f16 %0,h;}" : "=f"(f) : "r"(p));
    return f;
}

// ---------------- mma / ldsm / cp.async / named barriers ----------------
__device__ __forceinline__ void ldsm_x4(uint32_t r[4], uint32_t addr) {
    asm volatile("ldmatrix.sync.aligned.m8n8.x4.shared.b16 {%0,%1,%2,%3}, [%4];"
        : "=r"(r[0]), "=r"(r[1]), "=r"(r[2]), "=r"(r[3]) : "r"(addr));
}
__device__ __forceinline__ void ldsm_x4_t(uint32_t r[4], uint32_t addr) {
    asm volatile("ldmatrix.sync.aligned.m8n8.x4.trans.shared.b16 {%0,%1,%2,%3}, [%4];"
        : "=r"(r[0]), "=r"(r[1]), "=r"(r[2]), "=r"(r[3]) : "r"(addr));
}
__device__ __forceinline__ void mma16816h(float acc[4], const uint32_t a[4],
                                          uint32_t b0, uint32_t b1) {
    asm volatile(
        "mma.sync.aligned.m16n8k16.row.col.f32.f16.f16.f32 "
        "{%0,%1,%2,%3}, {%4,%5,%6,%7}, {%8,%9}, {%0,%1,%2,%3};\n"
        : "+f"(acc[0]), "+f"(acc[1]), "+f"(acc[2]), "+f"(acc[3])
        : "r"(a[0]), "r"(a[1]), "r"(a[2]), "r"(a[3]), "r"(b0), "r"(b1));
}
__device__ __forceinline__ void cp16(uint32_t dst, const void* src) {
    asm volatile("cp.async.cg.shared.global [%0], [%1], 16;" :: "r"(dst), "l"(src));
}
#define CP_COMMIT() asm volatile("cp.async.commit_group;" ::: "memory")
#define CP_WAIT0()  asm volatile("cp.async.wait_group 0;" ::: "memory")
#define BAR_SYNC(id)   asm volatile("bar.sync %0, 256;"   :: "r"(id) : "memory")
#define BAR_ARRIVE(id) asm volatile("bar.arrive %0, 256;" :: "r"(id) : "memory")

// ---------------------------------------------------------------
// Kernel 1: symmetric pack, upper-triangular grid
// ---------------------------------------------------------------
#define NT (SS / 32)
#define NPAIR (NT * (NT + 1) / 2)

__global__ void pack_code_kernel(const float* __restrict__ adj) {
    __shared__ float tA[32][33], tB[32][33];
    const int b = blockIdx.z;
    int rem = blockIdx.x;
    int It = 0;
    while (rem >= NT - It) { rem -= NT - It; It++; }
    const int I = It * 32;
    const int J = (It + rem) * 32;
    const int tx = threadIdx.x, ty = threadIdx.y;
    const float* A = adj + (size_t)b * SS * SS;

    tA[ty][tx] = A[(size_t)(I + ty) * SS + (J + tx)];
    tB[ty][tx] = A[(size_t)(J + ty) * SS + (I + tx)];
    __syncthreads();

    unsigned char cIJ = (tA[ty][tx] == 1.0f ? 1u : 0u) | (tB[tx][ty] == 1.0f ? 2u : 0u);
    unsigned char cJI = (tB[ty][tx] == 1.0f ? 1u : 0u) | (tA[tx][ty] == 1.0f ? 2u : 0u);
    g_code[((size_t)b * SS + (I + ty)) * SS + (J + tx)] = cIJ;
    g_code[((size_t)b * SS + (J + ty)) * SS + (I + tx)] = cJI;
}

// ---------------------------------------------------------------
// Kernel 2: sa/sb projections + f16 hi/lo split of h
// ---------------------------------------------------------------
__global__ void sasb_split_kernel(const float* __restrict__ hin,
                                  const float* __restrict__ w1,
                                  const float* __restrict__ w2,
                                  const float* __restrict__ bias_ptr,
                                  uint32_t* __restrict__ hi_out,
                                  uint32_t* __restrict__ lo_out) {
    const int tid  = threadIdx.x;
    const int lane = tid & 31;
    const int row  = blockIdx.x * 8 + (tid >> 5);
    if (row >= BB * SS) return;

    const float4 hv  = reinterpret_cast<const float4*>(hin)[(size_t)row * 32 + lane];
    const float4 w1v = reinterpret_cast<const float4*>(w1)[lane];
    const float4 w2v = reinterpret_cast<const float4*>(w2)[lane];

    {
        const uint32_t h01 = f2h2(hv.y, hv.x);
        const uint32_t h23 = f2h2(hv.w, hv.z);
        const float l0 = hv.x - hlo2f(h01);
        const float l1 = hv.y - hhi2f(h01);
        const float l2 = hv.z - hlo2f(h23);
        const float l3 = hv.w - hhi2f(h23);
        reinterpret_cast<uint2*>(hi_out)[(size_t)row * 32 + lane] = make_uint2(h01, h23);
        reinterpret_cast<uint2*>(lo_out)[(size_t)row * 32 + lane] =
            make_uint2(f2h2(l1, l0), f2h2(l3, l2));
    }

    float d1 = hv.x * w1v.x + hv.y * w1v.y + hv.z * w1v.z + hv.w * w1v.w;
    float d2 = hv.x * w2v.x + hv.y * w2v.y + hv.z * w2v.z + hv.w * w2v.w;
    #pragma unroll
    for (int off = 16; off > 0; off >>= 1) {
        d1 += __shfl_xor_sync(0xFFFFFFFFu, d1, off);
        d2 += __shfl_xor_sync(0xFFFFFFFFu, d2, off);
    }
    if (lane == 0) {
        g_sa[row] = d1 + bias_ptr[0];
        g_sb[row] = d2;
    }
}

// ---------------------------------------------------------------
// score quad (MUFU) -> single fp16 P
// ---------------------------------------------------------------
#define HLOG2E 0.721347520444f

__device__ __forceinline__ float quad4(uint32_t c4, const float4 sa4, const float4 sb4,
                                       const float sai, const float sbi,
                                       uint32_t& h01, uint32_t& h23) {
    float t1[4], t2[4];
    t1[0] = tanha(sai + sb4.x);  t1[1] = tanha(sai + sb4.y);
    t1[2] = tanha(sai + sb4.z);  t1[3] = tanha(sai + sb4.w);
    t2[0] = tanha(sa4.x + sbi);  t2[1] = tanha(sa4.y + sbi);
    t2[2] = tanha(sa4.z + sbi);  t2[3] = tanha(sa4.w + sbi);
    float e[4]; float es = 0.0f;
    #pragma unroll
    for (int k = 0; k < 4; k++) {
        const uint32_t c = (c4 >> (8 * k)) & 0xFFu;
        const float f1 = (c & 1u) ? t1[k] : 0.0f;
        const float f2 = (c & 2u) ? t2[k] : 0.0f;
        const float ev = ex2a((f1 + f2) * HLOG2E);
        e[k] = c ? ev : EPSM;
        es += e[k];
    }
    h01 = f2h2(e[1], e[0]);
    h23 = f2h2(e[3], e[2]);
    return es;
}

// ---------------------------------------------------------------
// Kernel 3: WARP-SPECIALIZED fused. 64 rows/block, 256 thr.
// Warps 0-3: MMA consumers (16 rows x 128 cols). Warps 4-7: E producers.
// P: single fp16 plane, 64 rows x 128B/chunk (SW swizzle), double-buffered.
// H: fp16 hi/lo, double-buffered. smem = 90624 B -> occ 2.
// ---------------------------------------------------------------
#define OFF_SA   0
#define OFF_SB   2048
#define OFF_RS   4096
#define OFF_P    4608
#define P_BUFSZ  8192
#define OFF_H    20992
#define H_PART   17408
#define H_BUFSZ  34816
#define SMEM_TOTAL 90624
#define LDHB 272

__global__ __launch_bounds__(256, 2)
void fused_layer_kernel(const uint32_t* __restrict__ hhi_in,
                        const uint32_t* __restrict__ hlo_in,
                        float* __restrict__ hout,
                        uint32_t* __restrict__ hhi_out,
                        uint32_t* __restrict__ hlo_out,
                        int write_split) {
    extern __shared__ char smem[];
    float* s_sa   = (float*)(smem + OFF_SA);
    float* s_sb   = (float*)(smem + OFF_SB);
    float* s_rsum = (float*)(smem + OFF_RS);
    const uint32_t su = (uint32_t)__cvta_generic_to_shared(smem);

    const int b    = blockIdx.y;
    const int i0   = blockIdx.x * 64;
    const int tid  = threadIdx.x;
    const int lane = tid & 31;
    const int w    = tid >> 5;

    #pragma unroll
    for (int q = 0; q < 2; q++) {
        int j = q * 256 + tid;
        s_sa[j] = g_sa[b * SS + j];
        s_sb[j] = g_sb[b * SS + j];
    }
    __syncthreads();

    if (w >= 4) {
        // =================== PRODUCER: E + H staging ===================
        const int et = tid - 128;
        const int er = et >> 1;             // row 0..63
        const int eq = et & 1;
        const float sai = s_sa[i0 + er];
        const float sbi = s_sb[i0 + er];
        const unsigned char* crow = g_code + ((size_t)b * SS + i0 + er) * SS;
        const uint32_t* hhiB = hhi_in + (size_t)b * SS * (HH / 2);
        const uint32_t* hloB = hlo_in + (size_t)b * SS * (HH / 2);
        float esum = 0.0f;

        for (int kc = 0; kc < 8; kc++) {
            const int buf = kc & 1;
            if (kc >= 2) BAR_SYNC(3 + buf);          // MMA done with this buf

            // stage H(kc) -> H buf
            {
                const uint32_t hb = su + OFF_H + buf * H_BUFSZ;
                #pragma unroll
                for (int t = 0; t < 8; t++) {
                    const int idx = t * 128 + et;
                    const int k = idx >> 4, g = idx & 15;
                    const uint32_t d = hb + k * LDHB + g * 16;
                    const size_t src = (size_t)(kc * 64 + k) * 64 + g * 4;
                    cp16(d,          hhiB + src);
                    cp16(d + H_PART, hloB + src);
                }
                CP_COMMIT();
            }

            // compute E(kc) -> P buf (single fp16 plane)
            {
                char* ph = smem + OFF_P + buf * P_BUFSZ + er * 128;
                #pragma unroll
                for (int u = 0; u < 4; u++) {
                    const int seg = eq * 4 + u;      // 16B unit 0..7
                    const int j0 = kc * 64 + seg * 8;
                    const ull codes = *(const ull*)(crow + j0);
                    const float4 sb0 = *(const float4*)(s_sb + j0);
                    const float4 sb1 = *(const float4*)(s_sb + j0 + 4);
                    const float4 sa0 = *(const float4*)(s_sa + j0);
                    const float4 sa1 = *(const float4*)(s_sa + j0 + 4);
                    uint32_t h0, h1, h2, h3;
                    esum += quad4((uint32_t)codes,         sa0, sb0, sai, sbi, h0, h1);
                    esum += quad4((uint32_t)(codes >> 32), sa1, sb1, sai, sbi, h2, h3);
                    const uint32_t phys = ((uint32_t)(seg ^ (er & 7))) * 16u;
                    *(uint4*)(ph + phys) = make_uint4(h0, h1, h2, h3);
                }
            }

            CP_WAIT0();                              // H(kc) landed
            BAR_ARRIVE(1 + buf);                     // publish P(kc)+H(kc)
        }

        esum += __shfl_xor_sync(0xFFFFFFFFu, esum, 1);
        if (eq == 0) s_rsum[er] = esum;
        BAR_SYNC(5);
    } else {
        // =================== CONSUMER: MMA + epilogue ===================
        const int m0 = w * 16;
        const int arow = m0 + (lane & 15);
        const int aunit0 = (lane >> 4);
        const int brow = (lane & 7) + ((lane >> 3) & 1) * 8;
        const uint32_t b_cb0 = (uint32_t)(((lane >> 4) * 8) * 2);

        float acc[16][4];
        #pragma unroll
        for (int nf = 0; nf < 16; nf++)
            #pragma unroll
            for (int q = 0; q < 4; q++) acc[nf][q] = 0.0f;

        for (int kc = 0; kc < 8; kc++) {
            const int buf = kc & 1;
            BAR_SYNC(1 + buf);                       // wait P(kc)+H(kc)

            const uint32_t pb = su + OFF_P + buf * P_BUFSZ + arow * 128;
            const uint32_t hb = su + OFF_H + buf * H_BUFSZ;
            #pragma unroll
            for (int s = 0; s < 4; s++) {
                const uint32_t phys = (((uint32_t)(s * 2 + aunit0)) ^ (uint32_t)(arow & 7)) * 16u;
                uint32_t a[4];
                ldsm_x4(a, pb + phys);
                const uint32_t brbase = hb + (uint32_t)((s * 16 + brow) * LDHB) + b_cb0;
                #pragma unroll
                for (int nn = 0; nn < 8; nn++) {
                    const uint32_t baddr = brbase + (uint32_t)(nn * 32);
                    uint32_t bh[4], bl[4];
                    ldsm_x4_t(bh, baddr);
                    ldsm_x4_t(bl, baddr + H_PART);
                    mma16816h(acc[2 * nn],     a, bh[0], bh[1]);
                    mma16816h(acc[2 * nn],     a, bl[0], bl[1]);
                    mma16816h(acc[2 * nn + 1], a, bh[2], bh[3]);
                    mma16816h(acc[2 * nn + 1], a, bl[2], bl[3]);
                }
            }

            if (kc < 6) BAR_ARRIVE(3 + buf);         // release buf for E(kc+2)
        }

        BAR_SYNC(5);                                 // rsum ready

        const int r0 = m0 + (lane >> 2);
        const float inv0 = 1.0f / s_rsum[r0];
        const float inv1 = 1.0f / s_rsum[r0 + 8];
        const size_t gr0 = ((size_t)b * SS + i0 + r0) * HH;
        const size_t gr1 = gr0 + 8 * HH;
        #pragma unroll
        for (int nf = 0; nf < 16; nf++) {
            const int col = nf * 8 + 2 * (lane & 3);
            const float v0 = acc[nf][0] * inv0, v1 = acc[nf][1] * inv0;
            const float v2 = acc[nf][2] * inv1, v3 = acc[nf][3] * inv1;
            *(float2*)(hout + gr0 + col) = make_float2(v0, v1);
            *(float2*)(hout + gr1 + col) = make_float2(v2, v3);

            if (write_split) {
                const uint32_t hp0 = f2h2(v1, v0);
                const uint32_t hp1 = f2h2(v3, v2);
                const float a0 = v0 - hlo2f(hp0);
                const float a1 = v1 - hhi2f(hp0);
                const float a2 = v2 - hlo2f(hp1);
                const float a3 = v3 - hhi2f(hp1);
                hhi_out[(gr0 + col) >> 1] = hp0;
                hlo_out[(gr0 + col) >> 1] = f2h2(a1, a0);
                hhi_out[(gr1 + col) >> 1] = hp1;
                hlo_out[(gr1 + col) >> 1] = f2h2(a3, a2);
            }
        }
    }
}

// ---------------------------------------------------------------
// Kernel 4: gather rows by alias_inputs
// ---------------------------------------------------------------
__global__ void gather_kernel(const float* __restrict__ hfin,
                              const int* __restrict__ alias,
                              float* __restrict__ out) {
    const int tid = blockIdx.x * blockDim.x + threadIdx.x;
    const int N4 = BB * SS * (HH / 4);
    if (tid >= N4) return;
    const int c4 = tid & 31;
    const int s  = (tid >> 5) & (SS - 1);
    const int b  = tid >> (5 + 9);
    const int a  = alias[b * SS + s];
    reinterpret_cast<float4*>(out)[tid] =
        reinterpret_cast<const float4*>(hfin)[((size_t)b * SS + a) * 32 + c4];
}

// ---------------------------------------------------------------
extern "C" void kernel_launch(void* const* d_in, const int* in_sizes, int n_in,
                              void* d_out, int out_size) {
    const float* hidden = (const float*)d_in[0];
    const float* adj    = (const float*)d_in[1];
    const int*   alias  = (const int*)d_in[2];
    const float* w1     = (const float*)d_in[3];
    const float* w2     = (const float*)d_in[4];
    const float* bias   = (const float*)d_in[5];
    float* out = (float*)d_out;

    cudaFuncSetAttribute(fused_layer_kernel,
                         cudaFuncAttributeMaxDynamicSharedMemorySize, SMEM_TOTAL);

    float* hb0;  cudaGetSymbolAddress((void**)&hb0, g_hbuf0);
    float* hb1;  cudaGetSymbolAddress((void**)&hb1, g_hbuf1);
    uint32_t* hhi; cudaGetSymbolAddress((void**)&hhi, g_hhi);
    uint32_t* hlo; cudaGetSymbolAddress((void**)&hlo, g_hlo);
    const size_t HC = (size_t)BB * SS * HH / 2;

    pack_code_kernel<<<dim3(NPAIR, 1, BB), dim3(32, 32)>>>(adj);

    sasb_split_kernel<<<(BB * SS) / 8, 256>>>(hidden, w1, w2, bias, hhi, hlo);
    fused_layer_kernel<<<dim3(SS / 64, BB), 256, SMEM_TOTAL>>>(
        hhi, hlo, hb0, hhi + HC, hlo + HC, 1);

    sasb_split_kernel<<<(BB * SS) / 8, 256>>>(hb0, w1, w2, bias, hhi, hlo);
    fused_layer_kernel<<<dim3(SS / 64, BB), 256, SMEM_TOTAL>>>(
        hhi + HC, hlo + HC, hb1, hhi, hlo, 0);

    const int N4 = BB * SS * (HH / 4);
    gather_kernel<<<(N4 + 255) / 256, 256>>>(hb1, alias, out);
}

// round 11
// speedup vs baseline: 2.4367x; 1.2513x over previous
#include <cuda_runtime.h>
#include <cuda_bf16.h>
#include <cuda_fp16.h>
#include <cstdint>

typedef unsigned long long ull;

#define BB 128
#define SS 512
#define HH 128
#define EPSM 5.9604644775390625e-08f   // 2^-24, exact fp16 subnormal

// -------- static device scratch --------
static __device__ unsigned char g_code[(size_t)BB * SS * SS];
static __device__ float g_hbuf1[(size_t)BB * SS * HH];
static __device__ uint32_t g_hhi[2][(size_t)BB * SS * HH / 2];  // f16x2 pairs
static __device__ uint32_t g_hlo[2][(size_t)BB * SS * HH / 2];
static __device__ float g_sav[2][BB * SS];
static __device__ float g_sbv[2][BB * SS];

// ---------------- fast math ----------------
__device__ __forceinline__ float tanha(float x) {
    float r; asm("tanh.approx.f32 %0,%1;" : "=f"(r) : "f"(x)); return r;
}
__device__ __forceinline__ float ex2a(float x) {
    float r; asm("ex2.approx.f32 %0,%1;" : "=f"(r) : "f"(x)); return r;
}
__device__ __forceinline__ uint32_t f2h2(float hi, float lo) {
    uint32_t r; asm("cvt.rn.f16x2.f32 %0,%1,%2;" : "=r"(r) : "f"(hi), "f"(lo)); return r;
}
__device__ __forceinline__ float hlo2f(uint32_t p) {
    float f; asm("{.reg .b16 l,h; mov.b32 {l,h},%1; cvt.f32.f16 %0,l;}" : "=f"(f) : "r"(p));
    return f;
}
__device__ __forceinline__ float hhi2f(uint32_t p) {
    float f; asm("{.reg .b16 l,h; mov.b32 {l,h},%1; cvt.f32.f16 %0,h;}" : "=f"(f) : "r"(p));
    return f;
}

// ---------------- mma / ldsm / cp.async / named barriers ----------------
__device__ __forceinline__ void ldsm_x4(uint32_t r[4], uint32_t addr) {
    asm volatile("ldmatrix.sync.aligned.m8n8.x4.shared.b16 {%0,%1,%2,%3}, [%4];"
        : "=r"(r[0]), "=r"(r[1]), "=r"(r[2]), "=r"(r[3]) : "r"(addr));
}
__device__ __forceinline__ void ldsm_x4_t(uint32_t r[4], uint32_t addr) {
    asm volatile("ldmatrix.sync.aligned.m8n8.x4.trans.shared.b16 {%0,%1,%2,%3}, [%4];"
        : "=r"(r[0]), "=r"(r[1]), "=r"(r[2]), "=r"(r[3]) : "r"(addr));
}
__device__ __forceinline__ void mma16816h(float acc[4], const uint32_t a[4],
                                          uint32_t b0, uint32_t b1) {
    asm volatile(
        "mma.sync.aligned.m16n8k16.row.col.f32.f16.f16.f32 "
        "{%0,%1,%2,%3}, {%4,%5,%6,%7}, {%8,%9}, {%0,%1,%2,%3};\n"
        : "+f"(acc[0]), "+f"(acc[1]), "+f"(acc[2]), "+f"(acc[3])
        : "r"(a[0]), "r"(a[1]), "r"(a[2]), "r"(a[3]), "r"(b0), "r"(b1));
}
__device__ __forceinline__ void cp16(uint32_t dst, const void* src) {
    asm volatile("cp.async.cg.shared.global [%0], [%1], 16;" :: "r"(dst), "l"(src));
}
#define CP_COMMIT() asm volatile("cp.async.commit_group;" ::: "memory")
#define CP_WAIT0()  asm volatile("cp.async.wait_group 0;" ::: "memory")
#define BAR_SYNC(id)   asm volatile("bar.sync %0, 256;"   :: "r"(id) : "memory")
#define BAR_ARRIVE(id) asm volatile("bar.arrive %0, 256;" :: "r"(id) : "memory")

// ---------------------------------------------------------------
// Kernel 1: symmetric pack, 64x64 pair-tiles, float4 loads
// ---------------------------------------------------------------
#define NT64 (SS / 64)                     // 8
#define NPAIR64 (NT64 * (NT64 + 1) / 2)    // 36

__global__ __launch_bounds__(256) void pack_code_kernel(const float* __restrict__ adj) {
    __shared__ float tA[64][65], tB[64][65];
    const int b = blockIdx.z;
    int rem = blockIdx.x;
    int It = 0;
    while (rem >= NT64 - It) { rem -= NT64 - It; It++; }
    const int I = It * 64;
    const int J = (It + rem) * 64;
    const int tid = threadIdx.x;
    const float* A = adj + (size_t)b * SS * SS;

    #pragma unroll
    for (int t = 0; t < 4; t++) {
        const int idx = t * 256 + tid;         // 0..1023
        const int r = idx >> 4, c4 = idx & 15;
        const float4 va = *(const float4*)(A + (size_t)(I + r) * SS + J + c4 * 4);
        const float4 vb = *(const float4*)(A + (size_t)(J + r) * SS + I + c4 * 4);
        tA[r][c4 * 4 + 0] = va.x; tA[r][c4 * 4 + 1] = va.y;
        tA[r][c4 * 4 + 2] = va.z; tA[r][c4 * 4 + 3] = va.w;
        tB[r][c4 * 4 + 0] = vb.x; tB[r][c4 * 4 + 1] = vb.y;
        tB[r][c4 * 4 + 2] = vb.z; tB[r][c4 * 4 + 3] = vb.w;
    }
    __syncthreads();

    #pragma unroll
    for (int t = 0; t < 4; t++) {
        const int idx = t * 256 + tid;
        const int r = idx >> 4, c4 = idx & 15;
        uchar4 cij, cji;
        unsigned char e0[4], e1[4];
        #pragma unroll
        for (int e = 0; e < 4; e++) {
            const int c = c4 * 4 + e;
            e0[e] = (tA[r][c] == 1.0f ? 1u : 0u) | (tB[c][r] == 1.0f ? 2u : 0u);
            e1[e] = (tB[r][c] == 1.0f ? 1u : 0u) | (tA[c][r] == 1.0f ? 2u : 0u);
        }
        cij = make_uchar4(e0[0], e0[1], e0[2], e0[3]);
        cji = make_uchar4(e1[0], e1[1], e1[2], e1[3]);
        *(uchar4*)(g_code + ((size_t)b * SS + I + r) * SS + J + c4 * 4) = cij;
        *(uchar4*)(g_code + ((size_t)b * SS + J + r) * SS + I + c4 * 4) = cji;
    }
}

// ---------------------------------------------------------------
// Kernel 2: sa/sb projections + f16 hi/lo split of input hidden
// ---------------------------------------------------------------
__global__ void sasb_split_kernel(const float* __restrict__ hin,
                                  const float* __restrict__ w1,
                                  const float* __restrict__ w2,
                                  const float* __restrict__ bias_ptr,
                                  uint32_t* __restrict__ hi_out,
                                  uint32_t* __restrict__ lo_out,
                                  float* __restrict__ sa_out,
                                  float* __restrict__ sb_out) {
    const int tid  = threadIdx.x;
    const int lane = tid & 31;
    const int row  = blockIdx.x * 8 + (tid >> 5);
    if (row >= BB * SS) return;

    const float4 hv  = reinterpret_cast<const float4*>(hin)[(size_t)row * 32 + lane];
    const float4 w1v = reinterpret_cast<const float4*>(w1)[lane];
    const float4 w2v = reinterpret_cast<const float4*>(w2)[lane];

    {
        const uint32_t h01 = f2h2(hv.y, hv.x);
        const uint32_t h23 = f2h2(hv.w, hv.z);
        const float l0 = hv.x - hlo2f(h01);
        const float l1 = hv.y - hhi2f(h01);
        const float l2 = hv.z - hlo2f(h23);
        const float l3 = hv.w - hhi2f(h23);
        reinterpret_cast<uint2*>(hi_out)[(size_t)row * 32 + lane] = make_uint2(h01, h23);
        reinterpret_cast<uint2*>(lo_out)[(size_t)row * 32 + lane] =
            make_uint2(f2h2(l1, l0), f2h2(l3, l2));
    }

    float d1 = hv.x * w1v.x + hv.y * w1v.y + hv.z * w1v.z + hv.w * w1v.w;
    float d2 = hv.x * w2v.x + hv.y * w2v.y + hv.z * w2v.z + hv.w * w2v.w;
    #pragma unroll
    for (int off = 16; off > 0; off >>= 1) {
        d1 += __shfl_xor_sync(0xFFFFFFFFu, d1, off);
        d2 += __shfl_xor_sync(0xFFFFFFFFu, d2, off);
    }
    if (lane == 0) {
        sa_out[row] = d1 + bias_ptr[0];
        sb_out[row] = d2;
    }
}

// ---------------------------------------------------------------
// score quad (MUFU) -> single fp16 P
// ---------------------------------------------------------------
#define HLOG2E 0.721347520444f

__device__ __forceinline__ float quad4(uint32_t c4, const float4 sa4, const float4 sb4,
                                       const float sai, const float sbi,
                                       uint32_t& h01, uint32_t& h23) {
    float t1[4], t2[4];
    t1[0] = tanha(sai + sb4.x);  t1[1] = tanha(sai + sb4.y);
    t1[2] = tanha(sai + sb4.z);  t1[3] = tanha(sai + sb4.w);
    t2[0] = tanha(sa4.x + sbi);  t2[1] = tanha(sa4.y + sbi);
    t2[2] = tanha(sa4.z + sbi);  t2[3] = tanha(sa4.w + sbi);
    float e[4]; float es = 0.0f;
    #pragma unroll
    for (int k = 0; k < 4; k++) {
        const uint32_t c = (c4 >> (8 * k)) & 0xFFu;
        const float f1 = (c & 1u) ? t1[k] : 0.0f;
        const float f2 = (c & 2u) ? t2[k] : 0.0f;
        const float ev = ex2a((f1 + f2) * HLOG2E);
        e[k] = c ? ev : EPSM;
        es += e[k];
    }
    h01 = f2h2(e[1], e[0]);
    h23 = f2h2(e[3], e[2]);
    return es;
}

// ---------------------------------------------------------------
// Kernel 3: WARP-SPECIALIZED fused. 64 rows/block, 256 thr, occ 2.
// mode=1 (layer 1): epilogue writes f16 split + next-layer sa/sb.
// mode=0 (layer 2): epilogue writes fp32 hout only.
// ---------------------------------------------------------------
#define OFF_SA   0
#define OFF_SB   2048
#define OFF_RS   4096
#define OFF_W1   4352
#define OFF_W2   4864
#define OFF_P    5376
#define P_BUFSZ  8192
#define OFF_H    21760
#define H_PART   17408
#define H_BUFSZ  34816
#define SMEM_TOTAL 91392
#define LDHB 272

__global__ __launch_bounds__(256, 2)
void fused_layer_kernel(const uint32_t* __restrict__ hhi_in,
                        const uint32_t* __restrict__ hlo_in,
                        const float* __restrict__ sa_in,
                        const float* __restrict__ sb_in,
                        float* __restrict__ hout,
                        uint32_t* __restrict__ hhi_out,
                        uint32_t* __restrict__ hlo_out,
                        float* __restrict__ sa_out,
                        float* __restrict__ sb_out,
                        const float* __restrict__ w1,
                        const float* __restrict__ w2,
                        const float* __restrict__ bias_ptr,
                        int mode) {
    extern __shared__ char smem[];
    float* s_sa   = (float*)(smem + OFF_SA);
    float* s_sb   = (float*)(smem + OFF_SB);
    float* s_rsum = (float*)(smem + OFF_RS);
    float* s_w1   = (float*)(smem + OFF_W1);
    float* s_w2   = (float*)(smem + OFF_W2);
    const uint32_t su = (uint32_t)__cvta_generic_to_shared(smem);

    const int b    = blockIdx.y;
    const int i0   = blockIdx.x * 64;
    const int tid  = threadIdx.x;
    const int lane = tid & 31;
    const int w    = tid >> 5;

    #pragma unroll
    for (int q = 0; q < 2; q++) {
        int j = q * 256 + tid;
        s_sa[j] = sa_in[b * SS + j];
        s_sb[j] = sb_in[b * SS + j];
    }
    if (tid < 128) s_w1[tid] = w1[tid];
    else           s_w2[tid - 128] = w2[tid - 128];
    __syncthreads();

    if (w >= 4) {
        // =================== PRODUCER: E + H staging ===================
        const int et = tid - 128;
        const int er = et >> 1;
        const int eq = et & 1;
        const float sai = s_sa[i0 + er];
        const float sbi = s_sb[i0 + er];
        const unsigned char* crow = g_code + ((size_t)b * SS + i0 + er) * SS;
        const uint32_t* hhiB = hhi_in + (size_t)b * SS * (HH / 2);
        const uint32_t* hloB = hlo_in + (size_t)b * SS * (HH / 2);
        float esum = 0.0f;

        for (int kc = 0; kc < 8; kc++) {
            const int buf = kc & 1;
            if (kc >= 2) BAR_SYNC(3 + buf);

            {
                const uint32_t hb = su + OFF_H + buf * H_BUFSZ;
                #pragma unroll
                for (int t = 0; t < 8; t++) {
                    const int idx = t * 128 + et;
                    const int k = idx >> 4, g = idx & 15;
                    const uint32_t d = hb + k * LDHB + g * 16;
                    const size_t src = (size_t)(kc * 64 + k) * 64 + g * 4;
                    cp16(d,          hhiB + src);
                    cp16(d + H_PART, hloB + src);
                }
                CP_COMMIT();
            }

            {
                char* ph = smem + OFF_P + buf * P_BUFSZ + er * 128;
                #pragma unroll
                for (int u = 0; u < 4; u++) {
                    const int seg = eq * 4 + u;
                    const int j0 = kc * 64 + seg * 8;
                    const ull codes = *(const ull*)(crow + j0);
                    const float4 sb0 = *(const float4*)(s_sb + j0);
                    const float4 sb1 = *(const float4*)(s_sb + j0 + 4);
                    const float4 sa0 = *(const float4*)(s_sa + j0);
                    const float4 sa1 = *(const float4*)(s_sa + j0 + 4);
                    uint32_t h0, h1, h2, h3;
                    esum += quad4((uint32_t)codes,         sa0, sb0, sai, sbi, h0, h1);
                    esum += quad4((uint32_t)(codes >> 32), sa1, sb1, sai, sbi, h2, h3);
                    const uint32_t phys = ((uint32_t)(seg ^ (er & 7))) * 16u;
                    *(uint4*)(ph + phys) = make_uint4(h0, h1, h2, h3);
                }
            }

            CP_WAIT0();
            BAR_ARRIVE(1 + buf);
        }

        esum += __shfl_xor_sync(0xFFFFFFFFu, esum, 1);
        if (eq == 0) s_rsum[er] = esum;
        BAR_SYNC(5);
    } else {
        // =================== CONSUMER: MMA + epilogue ===================
        const int m0 = w * 16;
        const int arow = m0 + (lane & 15);
        const int aunit0 = (lane >> 4);
        const int brow = (lane & 7) + ((lane >> 3) & 1) * 8;
        const uint32_t b_cb0 = (uint32_t)(((lane >> 4) * 8) * 2);

        float acc[16][4];
        #pragma unroll
        for (int nf = 0; nf < 16; nf++)
            #pragma unroll
            for (int q = 0; q < 4; q++) acc[nf][q] = 0.0f;

        for (int kc = 0; kc < 8; kc++) {
            const int buf = kc & 1;
            BAR_SYNC(1 + buf);

            const uint32_t pb = su + OFF_P + buf * P_BUFSZ + arow * 128;
            const uint32_t hb = su + OFF_H + buf * H_BUFSZ;
            #pragma unroll
            for (int s = 0; s < 4; s++) {
                const uint32_t phys = (((uint32_t)(s * 2 + aunit0)) ^ (uint32_t)(arow & 7)) * 16u;
                uint32_t a[4];
                ldsm_x4(a, pb + phys);
                const uint32_t brbase = hb + (uint32_t)((s * 16 + brow) * LDHB) + b_cb0;
                #pragma unroll
                for (int nn = 0; nn < 8; nn++) {
                    const uint32_t baddr = brbase + (uint32_t)(nn * 32);
                    uint32_t bh[4], bl[4];
                    ldsm_x4_t(bh, baddr);
                    ldsm_x4_t(bl, baddr + H_PART);
                    mma16816h(acc[2 * nn],     a, bh[0], bh[1]);
                    mma16816h(acc[2 * nn],     a, bl[0], bl[1]);
                    mma16816h(acc[2 * nn + 1], a, bh[2], bh[3]);
                    mma16816h(acc[2 * nn + 1], a, bl[2], bl[3]);
                }
            }

            if (kc < 6) BAR_ARRIVE(3 + buf);
        }

        BAR_SYNC(5);                                 // rsum ready

        const int r0 = m0 + (lane >> 2);
        const float inv0 = 1.0f / s_rsum[r0];
        const float inv1 = 1.0f / s_rsum[r0 + 8];
        const size_t gr0 = ((size_t)b * SS + i0 + r0) * HH;
        const size_t gr1 = gr0 + 8 * HH;

        if (mode) {
            // layer 1: write f16 split + accumulate next-layer sa/sb
            float d1a = 0.0f, d2a = 0.0f, d1b = 0.0f, d2b = 0.0f;
            #pragma unroll
            for (int nf = 0; nf < 16; nf++) {
                const int col = nf * 8 + 2 * (lane & 3);
                const float v0 = acc[nf][0] * inv0, v1 = acc[nf][1] * inv0;
                const float v2 = acc[nf][2] * inv1, v3 = acc[nf][3] * inv1;
                const float wa0 = s_w1[col], wa1 = s_w1[col + 1];
                const float wb0 = s_w2[col], wb1 = s_w2[col + 1];
                d1a += wa0 * v0 + wa1 * v1;  d2a += wb0 * v0 + wb1 * v1;
                d1b += wa0 * v2 + wa1 * v3;  d2b += wb0 * v2 + wb1 * v3;

                const uint32_t hp0 = f2h2(v1, v0);
                const uint32_t hp1 = f2h2(v3, v2);
                const float a0 = v0 - hlo2f(hp0);
                const float a1 = v1 - hhi2f(hp0);
                const float a2 = v2 - hlo2f(hp1);
                const float a3 = v3 - hhi2f(hp1);
                hhi_out[(gr0 + col) >> 1] = hp0;
                hlo_out[(gr0 + col) >> 1] = f2h2(a1, a0);
                hhi_out[(gr1 + col) >> 1] = hp1;
                hlo_out[(gr1 + col) >> 1] = f2h2(a3, a2);
            }
            // reduce over the 4 lanes sharing each row (lane&3 dims)
            #pragma unroll
            for (int off = 1; off <= 2; off <<= 1) {
                d1a += __shfl_xor_sync(0xFFFFFFFFu, d1a, off);
                d2a += __shfl_xor_sync(0xFFFFFFFFu, d2a, off);
                d1b += __shfl_xor_sync(0xFFFFFFFFu, d1b, off);
                d2b += __shfl_xor_sync(0xFFFFFFFFu, d2b, off);
            }
            if ((lane & 3) == 0) {
                const float bias = bias_ptr[0];
                sa_out[b * SS + i0 + r0] = d1a + bias;
                sb_out[b * SS + i0 + r0] = d2a;
                sa_out[b * SS + i0 + r0 + 8] = d1b + bias;
                sb_out[b * SS + i0 + r0 + 8] = d2b;
            }
        } else {
            // layer 2: write fp32 only
            #pragma unroll
            for (int nf = 0; nf < 16; nf++) {
                const int col = nf * 8 + 2 * (lane & 3);
                *(float2*)(hout + gr0 + col) =
                    make_float2(acc[nf][0] * inv0, acc[nf][1] * inv0);
                *(float2*)(hout + gr1 + col) =
                    make_float2(acc[nf][2] * inv1, acc[nf][3] * inv1);
            }
        }
    }
}

// ---------------------------------------------------------------
// Kernel 4: gather rows by alias_inputs
// ---------------------------------------------------------------
__global__ void gather_kernel(const float* __restrict__ hfin,
                              const int* __restrict__ alias,
                              float* __restrict__ out) {
    const int tid = blockIdx.x * blockDim.x + threadIdx.x;
    const int N4 = BB * SS * (HH / 4);
    if (tid >= N4) return;
    const int c4 = tid & 31;
    const int s  = (tid >> 5) & (SS - 1);
    const int b  = tid >> (5 + 9);
    const int a  = alias[b * SS + s];
    reinterpret_cast<float4*>(out)[tid] =
        reinterpret_cast<const float4*>(hfin)[((size_t)b * SS + a) * 32 + c4];
}

// ---------------------------------------------------------------
extern "C" void kernel_launch(void* const* d_in, const int* in_sizes, int n_in,
                              void* d_out, int out_size) {
    const float* hidden = (const float*)d_in[0];
    const float* adj    = (const float*)d_in[1];
    const int*   alias  = (const int*)d_in[2];
    const float* w1     = (const float*)d_in[3];
    const float* w2     = (const float*)d_in[4];
    const float* bias   = (const float*)d_in[5];
    float* out = (float*)d_out;

    cudaFuncSetAttribute(fused_layer_kernel,
                         cudaFuncAttributeMaxDynamicSharedMemorySize, SMEM_TOTAL);

    float* hb1;  cudaGetSymbolAddress((void**)&hb1, g_hbuf1);
    uint32_t* hhi; cudaGetSymbolAddress((void**)&hhi, g_hhi);
    uint32_t* hlo; cudaGetSymbolAddress((void**)&hlo, g_hlo);
    float* sav; cudaGetSymbolAddress((void**)&sav, g_sav);
    float* sbv; cudaGetSymbolAddress((void**)&sbv, g_sbv);
    const size_t HC = (size_t)BB * SS * HH / 2;
    const size_t SC = (size_t)BB * SS;

    pack_code_kernel<<<dim3(NPAIR64, 1, BB), 256>>>(adj);

    // layer 0 projections + split of input hidden -> slot 0
    sasb_split_kernel<<<(BB * SS) / 8, 256>>>(hidden, w1, w2, bias, hhi, hlo, sav, sbv);

    // layer 1: reads split0 + sa/sb0; writes split1 + sa/sb1
    fused_layer_kernel<<<dim3(SS / 64, BB), 256, SMEM_TOTAL>>>(
        hhi, hlo, sav, sbv, hb1, hhi + HC, hlo + HC, sav + SC, sbv + SC,
        w1, w2, bias, 1);

    // layer 2: reads split1 + sa/sb1; writes fp32 hb1
    fused_layer_kernel<<<dim3(SS / 64, BB), 256, SMEM_TOTAL>>>(
        hhi + HC, hlo + HC, sav + SC, sbv + SC, hb1, hhi, hlo, sav, sbv,
        w1, w2, bias, 0);

    const int N4 = BB * SS * (HH / 4);
    gather_kernel<<<(N4 + 255) / 256, 256>>>(hb1, alias, out);
}

// round 12
// speedup vs baseline: 2.4370x; 1.0001x over previous
#include <cuda_runtime.h>
#include <cuda_bf16.h>
#include <cuda_fp16.h>
#include <cstdint>

typedef unsigned long long ull;

#define BB 128
#define SS 512
#define HH 128
#define EPSM 5.9604644775390625e-08f   // 2^-24, exact fp16 subnormal

// -------- static device scratch --------
static __device__ unsigned char g_code[(size_t)BB * SS * SS];
static __device__ float g_hbuf1[(size_t)BB * SS * HH];
static __device__ uint32_t g_hhi[2][(size_t)BB * SS * HH / 2];  // f16x2 pairs
static __device__ uint32_t g_hlo[2][(size_t)BB * SS * HH / 2];
static __device__ float g_sav[2][BB * SS];
static __device__ float g_sbv[2][BB * SS];

// ---------------- fast math ----------------
__device__ __forceinline__ float tanha(float x) {
    float r; asm("tanh.approx.f32 %0,%1;" : "=f"(r) : "f"(x)); return r;
}
__device__ __forceinline__ float ex2a(float x) {
    float r; asm("ex2.approx.f32 %0,%1;" : "=f"(r) : "f"(x)); return r;
}
__device__ __forceinline__ uint32_t f2h2(float hi, float lo) {
    uint32_t r; asm("cvt.rn.f16x2.f32 %0,%1,%2;" : "=r"(r) : "f"(hi), "f"(lo)); return r;
}
__device__ __forceinline__ float hlo2f(uint32_t p) {
    float f; asm("{.reg .b16 l,h; mov.b32 {l,h},%1; cvt.f32.f16 %0,l;}" : "=f"(f) : "r"(p));
    return f;
}
__device__ __forceinline__ float hhi2f(uint32_t p) {
    float f; asm("{.reg .b16 l,h; mov.b32 {l,h},%1; cvt.f32.f16 %0,h;}" : "=f"(f) : "r"(p));
    return f;
}

// ---------------- mma / ldsm / cp.async / named barriers ----------------
__device__ __forceinline__ void ldsm_x4(uint32_t r[4], uint32_t addr) {
    asm volatile("ldmatrix.sync.aligned.m8n8.x4.shared.b16 {%0,%1,%2,%3}, [%4];"
        : "=r"(r[0]), "=r"(r[1]), "=r"(r[2]), "=r"(r[3]) : "r"(addr));
}
__device__ __forceinline__ void ldsm_x4_t(uint32_t r[4], uint32_t addr) {
    asm volatile("ldmatrix.sync.aligned.m8n8.x4.trans.shared.b16 {%0,%1,%2,%3}, [%4];"
        : "=r"(r[0]), "=r"(r[1]), "=r"(r[2]), "=r"(r[3]) : "r"(addr));
}
__device__ __forceinline__ void mma16816h(float acc[4], const uint32_t a[4],
                                          uint32_t b0, uint32_t b1) {
    asm volatile(
        "mma.sync.aligned.m16n8k16.row.col.f32.f16.f16.f32 "
        "{%0,%1,%2,%3}, {%4,%5,%6,%7}, {%8,%9}, {%0,%1,%2,%3};\n"
        : "+f"(acc[0]), "+f"(acc[1]), "+f"(acc[2]), "+f"(acc[3])
        : "r"(a[0]), "r"(a[1]), "r"(a[2]), "r"(a[3]), "r"(b0), "r"(b1));
}
__device__ __forceinline__ void cp16(uint32_t dst, const void* src) {
    asm volatile("cp.async.cg.shared.global [%0], [%1], 16;" :: "r"(dst), "l"(src));
}
#define CP_COMMIT() asm volatile("cp.async.commit_group;" ::: "memory")
#define CP_WAIT0()  asm volatile("cp.async.wait_group 0;" ::: "memory")
#define BAR_SYNC(id)   asm volatile("bar.sync %0, 256;"   :: "r"(id) : "memory")
#define BAR_ARRIVE(id) asm volatile("bar.arrive %0, 256;" :: "r"(id) : "memory")

// ---------------------------------------------------------------
// Kernel 1: symmetric pack, 64x64 pair-tiles, float4 loads
// ---------------------------------------------------------------
#define NT64 (SS / 64)                     // 8
#define NPAIR64 (NT64 * (NT64 + 1) / 2)    // 36

__global__ __launch_bounds__(256) void pack_code_kernel(const float* __restrict__ adj) {
    __shared__ float tA[64][65], tB[64][65];
    const int b = blockIdx.z;
    int rem = blockIdx.x;
    int It = 0;
    while (rem >= NT64 - It) { rem -= NT64 - It; It++; }
    const int I = It * 64;
    const int J = (It + rem) * 64;
    const int tid = threadIdx.x;
    const float* A = adj + (size_t)b * SS * SS;

    #pragma unroll
    for (int t = 0; t < 4; t++) {
        const int idx = t * 256 + tid;         // 0..1023
        const int r = idx >> 4, c4 = idx & 15;
        const float4 va = *(const float4*)(A + (size_t)(I + r) * SS + J + c4 * 4);
        const float4 vb = *(const float4*)(A + (size_t)(J + r) * SS + I + c4 * 4);
        tA[r][c4 * 4 + 0] = va.x; tA[r][c4 * 4 + 1] = va.y;
        tA[r][c4 * 4 + 2] = va.z; tA[r][c4 * 4 + 3] = va.w;
        tB[r][c4 * 4 + 0] = vb.x; tB[r][c4 * 4 + 1] = vb.y;
        tB[r][c4 * 4 + 2] = vb.z; tB[r][c4 * 4 + 3] = vb.w;
    }
    __syncthreads();

    #pragma unroll
    for (int t = 0; t < 4; t++) {
        const int idx = t * 256 + tid;
        const int r = idx >> 4, c4 = idx & 15;
        uchar4 cij, cji;
        unsigned char e0[4], e1[4];
        #pragma unroll
        for (int e = 0; e < 4; e++) {
            const int c = c4 * 4 + e;
            e0[e] = (tA[r][c] == 1.0f ? 1u : 0u) | (tB[c][r] == 1.0f ? 2u : 0u);
            e1[e] = (tB[r][c] == 1.0f ? 1u : 0u) | (tA[c][r] == 1.0f ? 2u : 0u);
        }
        cij = make_uchar4(e0[0], e0[1], e0[2], e0[3]);
        cji = make_uchar4(e1[0], e1[1], e1[2], e1[3]);
        *(uchar4*)(g_code + ((size_t)b * SS + I + r) * SS + J + c4 * 4) = cij;
        *(uchar4*)(g_code + ((size_t)b * SS + J + r) * SS + I + c4 * 4) = cji;
    }
}

// ---------------------------------------------------------------
// Kernel 2: sa/sb projections + f16 hi/lo split of input hidden
// ---------------------------------------------------------------
__global__ void sasb_split_kernel(const float* __restrict__ hin,
                                  const float* __restrict__ w1,
                                  const float* __restrict__ w2,
                                  const float* __restrict__ bias_ptr,
                                  uint32_t* __restrict__ hi_out,
                                  uint32_t* __restrict__ lo_out,
                                  float* __restrict__ sa_out,
                                  float* __restrict__ sb_out) {
    const int tid  = threadIdx.x;
    const int lane = tid & 31;
    const int row  = blockIdx.x * 8 + (tid >> 5);
    if (row >= BB * SS) return;

    const float4 hv  = reinterpret_cast<const float4*>(hin)[(size_t)row * 32 + lane];
    const float4 w1v = reinterpret_cast<const float4*>(w1)[lane];
    const float4 w2v = reinterpret_cast<const float4*>(w2)[lane];

    {
        const uint32_t h01 = f2h2(hv.y, hv.x);
        const uint32_t h23 = f2h2(hv.w, hv.z);
        const float l0 = hv.x - hlo2f(h01);
        const float l1 = hv.y - hhi2f(h01);
        const float l2 = hv.z - hlo2f(h23);
        const float l3 = hv.w - hhi2f(h23);
        reinterpret_cast<uint2*>(hi_out)[(size_t)row * 32 + lane] = make_uint2(h01, h23);
        reinterpret_cast<uint2*>(lo_out)[(size_t)row * 32 + lane] =
            make_uint2(f2h2(l1, l0), f2h2(l3, l2));
    }

    float d1 = hv.x * w1v.x + hv.y * w1v.y + hv.z * w1v.z + hv.w * w1v.w;
    float d2 = hv.x * w2v.x + hv.y * w2v.y + hv.z * w2v.z + hv.w * w2v.w;
    #pragma unroll
    for (int off = 16; off > 0; off >>= 1) {
        d1 += __shfl_xor_sync(0xFFFFFFFFu, d1, off);
        d2 += __shfl_xor_sync(0xFFFFFFFFu, d2, off);
    }
    if (lane == 0) {
        sa_out[row] = d1 + bias_ptr[0];
        sb_out[row] = d2;
    }
}

// ---------------------------------------------------------------
// score quad (MUFU) -> single fp16 P
// ---------------------------------------------------------------
#define HLOG2E 0.721347520444f

__device__ __forceinline__ float quad4(uint32_t c4, const float4 sa4, const float4 sb4,
                                       const float sai, const float sbi,
                                       uint32_t& h01, uint32_t& h23) {
    float t1[4], t2[4];
    t1[0] = tanha(sai + sb4.x);  t1[1] = tanha(sai + sb4.y);
    t1[2] = tanha(sai + sb4.z);  t1[3] = tanha(sai + sb4.w);
    t2[0] = tanha(sa4.x + sbi);  t2[1] = tanha(sa4.y + sbi);
    t2[2] = tanha(sa4.z + sbi);  t2[3] = tanha(sa4.w + sbi);
    float e[4]; float es = 0.0f;
    #pragma unroll
    for (int k = 0; k < 4; k++) {
        const uint32_t c = (c4 >> (8 * k)) & 0xFFu;
        const float f1 = (c & 1u) ? t1[k] : 0.0f;
        const float f2 = (c & 2u) ? t2[k] : 0.0f;
        const float ev = ex2a((f1 + f2) * HLOG2E);
        e[k] = c ? ev : EPSM;
        es += e[k];
    }
    h01 = f2h2(e[1], e[0]);
    h23 = f2h2(e[3], e[2]);
    return es;
}

// ---------------------------------------------------------------
// Kernel 3: WARP-SPECIALIZED fused. 64 rows/block, 256 thr, occ 2.
// mode=1 (layer 1): epilogue writes f16 split + next-layer sa/sb.
// mode=0 (layer 2): epilogue writes fp32 hout only.
// ---------------------------------------------------------------
#define OFF_SA   0
#define OFF_SB   2048
#define OFF_RS   4096
#define OFF_W1   4352
#define OFF_W2   4864
#define OFF_P    5376
#define P_BUFSZ  8192
#define OFF_H    21760
#define H_PART   17408
#define H_BUFSZ  34816
#define SMEM_TOTAL 91392
#define LDHB 272

__global__ __launch_bounds__(256, 2)
void fused_layer_kernel(const uint32_t* __restrict__ hhi_in,
                        const uint32_t* __restrict__ hlo_in,
                        const float* __restrict__ sa_in,
                        const float* __restrict__ sb_in,
                        float* __restrict__ hout,
                        uint32_t* __restrict__ hhi_out,
                        uint32_t* __restrict__ hlo_out,
                        float* __restrict__ sa_out,
                        float* __restrict__ sb_out,
                        const float* __restrict__ w1,
                        const float* __restrict__ w2,
                        const float* __restrict__ bias_ptr,
                        int mode) {
    extern __shared__ char smem[];
    float* s_sa   = (float*)(smem + OFF_SA);
    float* s_sb   = (float*)(smem + OFF_SB);
    float* s_rsum = (float*)(smem + OFF_RS);
    float* s_w1   = (float*)(smem + OFF_W1);
    float* s_w2   = (float*)(smem + OFF_W2);
    const uint32_t su = (uint32_t)__cvta_generic_to_shared(smem);

    const int b    = blockIdx.y;
    const int i0   = blockIdx.x * 64;
    const int tid  = threadIdx.x;
    const int lane = tid & 31;
    const int w    = tid >> 5;

    #pragma unroll
    for (int q = 0; q < 2; q++) {
        int j = q * 256 + tid;
        s_sa[j] = sa_in[b * SS + j];
        s_sb[j] = sb_in[b * SS + j];
    }
    if (tid < 128) s_w1[tid] = w1[tid];
    else           s_w2[tid - 128] = w2[tid - 128];
    __syncthreads();

    if (w >= 4) {
        // =================== PRODUCER: E + H staging ===================
        const int et = tid - 128;
        const int er = et >> 1;
        const int eq = et & 1;
        const float sai = s_sa[i0 + er];
        const float sbi = s_sb[i0 + er];
        const unsigned char* crow = g_code + ((size_t)b * SS + i0 + er) * SS;
        const uint32_t* hhiB = hhi_in + (size_t)b * SS * (HH / 2);
        const uint32_t* hloB = hlo_in + (size_t)b * SS * (HH / 2);
        float esum = 0.0f;

        for (int kc = 0; kc < 8; kc++) {
            const int buf = kc & 1;
            if (kc >= 2) BAR_SYNC(3 + buf);

            {
                const uint32_t hb = su + OFF_H + buf * H_BUFSZ;
                #pragma unroll
                for (int t = 0; t < 8; t++) {
                    const int idx = t * 128 + et;
                    const int k = idx >> 4, g = idx & 15;
                    const uint32_t d = hb + k * LDHB + g * 16;
                    const size_t src = (size_t)(kc * 64 + k) * 64 + g * 4;
                    cp16(d,          hhiB + src);
                    cp16(d + H_PART, hloB + src);
                }
                CP_COMMIT();
            }

            {
                char* ph = smem + OFF_P + buf * P_BUFSZ + er * 128;
                #pragma unroll
                for (int u = 0; u < 4; u++) {
                    const int seg = eq * 4 + u;
                    const int j0 = kc * 64 + seg * 8;
                    const ull codes = *(const ull*)(crow + j0);
                    const float4 sb0 = *(const float4*)(s_sb + j0);
                    const float4 sb1 = *(const float4*)(s_sb + j0 + 4);
                    const float4 sa0 = *(const float4*)(s_sa + j0);
                    const float4 sa1 = *(const float4*)(s_sa + j0 + 4);
                    uint32_t h0, h1, h2, h3;
                    esum += quad4((uint32_t)codes,         sa0, sb0, sai, sbi, h0, h1);
                    esum += quad4((uint32_t)(codes >> 32), sa1, sb1, sai, sbi, h2, h3);
                    const uint32_t phys = ((uint32_t)(seg ^ (er & 7))) * 16u;
                    *(uint4*)(ph + phys) = make_uint4(h0, h1, h2, h3);
                }
            }

            CP_WAIT0();
            BAR_ARRIVE(1 + buf);
        }

        esum += __shfl_xor_sync(0xFFFFFFFFu, esum, 1);
        if (eq == 0) s_rsum[er] = esum;
        BAR_SYNC(5);
    } else {
        // =================== CONSUMER: MMA + epilogue ===================
        const int m0 = w * 16;
        const int arow = m0 + (lane & 15);
        const int aunit0 = (lane >> 4);
        const int brow = (lane & 7) + ((lane >> 3) & 1) * 8;
        const uint32_t b_cb0 = (uint32_t)(((lane >> 4) * 8) * 2);

        float acc[16][4];
        #pragma unroll
        for (int nf = 0; nf < 16; nf++)
            #pragma unroll
            for (int q = 0; q < 4; q++) acc[nf][q] = 0.0f;

        for (int kc = 0; kc < 8; kc++) {
            const int buf = kc & 1;
            BAR_SYNC(1 + buf);

            const uint32_t pb = su + OFF_P + buf * P_BUFSZ + arow * 128;
            const uint32_t hb = su + OFF_H + buf * H_BUFSZ;
            #pragma unroll
            for (int s = 0; s < 4; s++) {
                const uint32_t phys = (((uint32_t)(s * 2 + aunit0)) ^ (uint32_t)(arow & 7)) * 16u;
                uint32_t a[4];
                ldsm_x4(a, pb + phys);
                const uint32_t brbase = hb + (uint32_t)((s * 16 + brow) * LDHB) + b_cb0;
                #pragma unroll
                for (int nn = 0; nn < 8; nn++) {
                    const uint32_t baddr = brbase + (uint32_t)(nn * 32);
                    uint32_t bh[4], bl[4];
                    ldsm_x4_t(bh, baddr);
                    ldsm_x4_t(bl, baddr + H_PART);
                    mma16816h(acc[2 * nn],     a, bh[0], bh[1]);
                    mma16816h(acc[2 * nn],     a, bl[0], bl[1]);
                    mma16816h(acc[2 * nn + 1], a, bh[2], bh[3]);
                    mma16816h(acc[2 * nn + 1], a, bl[2], bl[3]);
                }
            }

            if (kc < 6) BAR_ARRIVE(3 + buf);
        }

        BAR_SYNC(5);                                 // rsum ready

        const int r0 = m0 + (lane >> 2);
        const float inv0 = 1.0f / s_rsum[r0];
        const float inv1 = 1.0f / s_rsum[r0 + 8];
        const size_t gr0 = ((size_t)b * SS + i0 + r0) * HH;
        const size_t gr1 = gr0 + 8 * HH;

        if (mode) {
            // layer 1: write f16 split + accumulate next-layer sa/sb
            float d1a = 0.0f, d2a = 0.0f, d1b = 0.0f, d2b = 0.0f;
            #pragma unroll
            for (int nf = 0; nf < 16; nf++) {
                const int col = nf * 8 + 2 * (lane & 3);
                const float v0 = acc[nf][0] * inv0, v1 = acc[nf][1] * inv0;
                const float v2 = acc[nf][2] * inv1, v3 = acc[nf][3] * inv1;
                const float wa0 = s_w1[col], wa1 = s_w1[col + 1];
                const float wb0 = s_w2[col], wb1 = s_w2[col + 1];
                d1a += wa0 * v0 + wa1 * v1;  d2a += wb0 * v0 + wb1 * v1;
                d1b += wa0 * v2 + wa1 * v3;  d2b += wb0 * v2 + wb1 * v3;

                const uint32_t hp0 = f2h2(v1, v0);
                const uint32_t hp1 = f2h2(v3, v2);
                const float a0 = v0 - hlo2f(hp0);
                const float a1 = v1 - hhi2f(hp0);
                const float a2 = v2 - hlo2f(hp1);
                const float a3 = v3 - hhi2f(hp1);
                hhi_out[(gr0 + col) >> 1] = hp0;
                hlo_out[(gr0 + col) >> 1] = f2h2(a1, a0);
                hhi_out[(gr1 + col) >> 1] = hp1;
                hlo_out[(gr1 + col) >> 1] = f2h2(a3, a2);
            }
            // reduce over the 4 lanes sharing each row (lane&3 dims)
            #pragma unroll
            for (int off = 1; off <= 2; off <<= 1) {
                d1a += __shfl_xor_sync(0xFFFFFFFFu, d1a, off);
                d2a += __shfl_xor_sync(0xFFFFFFFFu, d2a, off);
                d1b += __shfl_xor_sync(0xFFFFFFFFu, d1b, off);
                d2b += __shfl_xor_sync(0xFFFFFFFFu, d2b, off);
            }
            if ((lane & 3) == 0) {
                const float bias = bias_ptr[0];
                sa_out[b * SS + i0 + r0] = d1a + bias;
                sb_out[b * SS + i0 + r0] = d2a;
                sa_out[b * SS + i0 + r0 + 8] = d1b + bias;
                sb_out[b * SS + i0 + r0 + 8] = d2b;
            }
        } else {
            // layer 2: write fp32 only
            #pragma unroll
            for (int nf = 0; nf < 16; nf++) {
                const int col = nf * 8 + 2 * (lane & 3);
                *(float2*)(hout + gr0 + col) =
                    make_float2(acc[nf][0] * inv0, acc[nf][1] * inv0);
                *(float2*)(hout + gr1 + col) =
                    make_float2(acc[nf][2] * inv1, acc[nf][3] * inv1);
            }
        }
    }
}

// ---------------------------------------------------------------
// Kernel 4: gather rows by alias_inputs
// ---------------------------------------------------------------
__global__ void gather_kernel(const float* __restrict__ hfin,
                              const int* __restrict__ alias,
                              float* __restrict__ out) {
    const int tid = blockIdx.x * blockDim.x + threadIdx.x;
    const int N4 = BB * SS * (HH / 4);
    if (tid >= N4) return;
    const int c4 = tid & 31;
    const int s  = (tid >> 5) & (SS - 1);
    const int b  = tid >> (5 + 9);
    const int a  = alias[b * SS + s];
    reinterpret_cast<float4*>(out)[tid] =
        reinterpret_cast<const float4*>(hfin)[((size_t)b * SS + a) * 32 + c4];
}

// ---------------------------------------------------------------
extern "C" void kernel_launch(void* const* d_in, const int* in_sizes, int n_in,
                              void* d_out, int out_size) {
    const float* hidden = (const float*)d_in[0];
    const float* adj    = (const float*)d_in[1];
    const int*   alias  = (const int*)d_in[2];
    const float* w1     = (const float*)d_in[3];
    const float* w2     = (const float*)d_in[4];
    const float* bias   = (const float*)d_in[5];
    float* out = (float*)d_out;

    cudaFuncSetAttribute(fused_layer_kernel,
                         cudaFuncAttributeMaxDynamicSharedMemorySize, SMEM_TOTAL);

    float* hb1;  cudaGetSymbolAddress((void**)&hb1, g_hbuf1);
    uint32_t* hhi; cudaGetSymbolAddress((void**)&hhi, g_hhi);
    uint32_t* hlo; cudaGetSymbolAddress((void**)&hlo, g_hlo);
    float* sav; cudaGetSymbolAddress((void**)&sav, g_sav);
    float* sbv; cudaGetSymbolAddress((void**)&sbv, g_sbv);
    const size_t HC = (size_t)BB * SS * HH / 2;
    const size_t SC = (size_t)BB * SS;

    pack_code_kernel<<<dim3(NPAIR64, 1, BB), 256>>>(adj);

    // layer 0 projections + split of input hidden -> slot 0
    sasb_split_kernel<<<(BB * SS) / 8, 256>>>(hidden, w1, w2, bias, hhi, hlo, sav, sbv);

    // layer 1: reads split0 + sa/sb0; writes split1 + sa/sb1
    fused_layer_kernel<<<dim3(SS / 64, BB), 256, SMEM_TOTAL>>>(
        hhi, hlo, sav, sbv, hb1, hhi + HC, hlo + HC, sav + SC, sbv + SC,
        w1, w2, bias, 1);

    // layer 2: reads split1 + sa/sb1; writes fp32 hb1
    fused_layer_kernel<<<dim3(SS / 64, BB), 256, SMEM_TOTAL>>>(
        hhi + HC, hlo + HC, sav + SC, sbv + SC, hb1, hhi, hlo, sav, sbv,
        w1, w2, bias, 0);

    const int N4 = BB * SS * (HH / 4);
    gather_kernel<<<(N4 + 255) / 256, 256>>>(hb1, alias, out);
}